// round 8
// baseline (speedup 1.0000x reference)
#include <cuda_runtime.h>
#include <cstdint>

// FullFixedTimeCausalConstructiveAttention — mma.sync m16n8k8 tf32 flash attn.
// Round 7: permuted smem layout (word pos = ((e&7+key)&7)*8 + e>>3) makes each
// thread's 8 B-fragment words contiguous -> LDS.128 fragment loads (4 per GEMM
// per chunk instead of 16 scalar LDS). 4 independent QK MMA chains.

#define B_ 8
#define L_ 1024
#define H_ 8
#define E_ 64
#define BQ 64
#define BK 128
#define NTH 128
#define KSTR 68     // row stride in words for K and V tiles

#define SM_DIAG 0
#define SM_K 256
#define SM_V (SM_K + BK*KSTR*4)
#define SMEM_TOTAL (SM_V + BK*KSTR*4)

typedef unsigned u32;

__device__ __forceinline__ u32 f2tf(float x){ u32 u;
  asm("cvt.rna.tf32.f32 %0, %1;":"=r"(u):"f"(x)); return u; }

#define MMA(d, a0,a1,a2,a3, b0,b1) \
  asm volatile("mma.sync.aligned.m16n8k8.row.col.f32.tf32.tf32.f32 " \
    "{%0,%1,%2,%3}, {%4,%5,%6,%7}, {%8,%9}, {%0,%1,%2,%3};" \
    : "+f"((d)[0]),"+f"((d)[1]),"+f"((d)[2]),"+f"((d)[3]) \
    : "r"(a0),"r"(a1),"r"(a2),"r"(a3), "r"(b0),"r"(b1))

__global__ void __launch_bounds__(NTH, 3)
ffcca_mma(const float* __restrict__ Q, const float* __restrict__ K,
          const float* __restrict__ V, const float* __restrict__ Qd,
          const float* __restrict__ Kd, const float* __restrict__ Vd,
          const int* __restrict__ histp, float* __restrict__ Out)
{
    extern __shared__ char smem[];
    float* sdiag = (float*)(smem + SM_DIAG);
    u32* Kt = (u32*)(smem + SM_K);
    u32* Vt = (u32*)(smem + SM_V);

    const int hist = *histp;                 // 512
    const int t = threadIdx.x;
    const int w = t >> 5, lane = t & 31;
    const int gid = lane >> 2, tig = lane & 3;
    const int qt = blockIdx.x, bh = blockIdx.y;
    const int b = bh >> 3, h = bh & 7;
    const int m0 = qt * BQ;
    const size_t rs = (size_t)H_ * E_;       // 512 floats per l
    const size_t base = (size_t)b * L_ * rs + (size_t)h * E_;

    const int rlo = m0 + w*16 + gid;         // this lane's two rows
    const int rhi = rlo + 8;

    // ---- exact fp32 diagonal scores for rows m0..m0+63 ----
    if (t < BQ) {
        int row = m0 + t;
        const float* qs = (row < hist) ? Q : Qd;
        const float4* qr = (const float4*)(qs + base + (size_t)row*rs);
        const float4* kr = (const float4*)(Kd + base + (size_t)row*rs);
        float a0=0,a1=0,a2=0,a3=0;
        #pragma unroll
        for (int c=0;c<16;c++){ float4 q4=qr[c], k4=kr[c];
            a0+=q4.x*k4.x; a1+=q4.y*k4.y; a2+=q4.z*k4.z; a3+=q4.w*k4.w; }
        sdiag[t] = (a0+a1)+(a2+a3);
    }

    // ---- Q fragments (hi + residual lo) for this warp's 16 rows ----
    u32 qf[8][4], ql[8][4];
    {
        const float* qs = (rlo < hist) ? Q : Qd;   // 16-row block is hist-uniform
        const float* qlo = qs + base + (size_t)rlo*rs;
        const float* qhi = qs + base + (size_t)rhi*rs;
        #pragma unroll
        for (int s=0;s<8;s++){
            float v0 = qlo[8*s+tig],   v1 = qhi[8*s+tig];
            float v2 = qlo[8*s+tig+4], v3 = qhi[8*s+tig+4];
            qf[s][0]=f2tf(v0); qf[s][1]=f2tf(v1); qf[s][2]=f2tf(v2); qf[s][3]=f2tf(v3);
            ql[s][0]=f2tf(v0-__uint_as_float(qf[s][0]));
            ql[s][1]=f2tf(v1-__uint_as_float(qf[s][1]));
            ql[s][2]=f2tf(v2-__uint_as_float(qf[s][2]));
            ql[s][3]=f2tf(v3-__uint_as_float(qf[s][3]));
        }
    }

    __syncthreads();                         // sdiag visible
    const float dlo = sdiag[rlo - m0];
    const float dhi = sdiag[rhi - m0];

    float o[8][4];
    #pragma unroll
    for (int j=0;j<8;j++){ o[j][0]=o[j][1]=o[j][2]=o[j][3]=0.f; }
    float sumlo=0.f, sumhi=0.f;

    const int wlmax = (m0 + w*16) + 15;      // warp's max query row
    const int ntiles = (m0 + BQ + BK - 1) / BK;
    const int src0 = (lane & ~3) | (tig >> 1);
    const int src1 = src0 + 2;
    const bool oddm = (tig & 1) != 0;

    // permuted group offsets (words), constant per thread
    const int gq0 = ((tig + gid) & 7) * 8;          // QK b0 group
    const int gq1 = ((tig + 4 + gid) & 7) * 8;      // QK b1 group
    const int gvA = ((gid + tig) & 7) * 8;          // PV b0 group (row&7 = tig)
    const int gvB = ((gid + tig + 4) & 7) * 8;      // PV b1 group (row&7 = tig+4)

    for (int nt = 0; nt < ntiles; nt++) {
        const int nb = nt * BK;
        __syncthreads();                     // previous tile fully consumed
        // ---- cooperative K/V tile load with permuted scatter store ----
        {
            const float4* kg = (const float4*)(K + base + (size_t)nb*rs);
            const float4* vg = (const float4*)(V + base + (size_t)nb*rs);
            #pragma unroll
            for (int i=0;i<16;i++){
                int idx = t + i*NTH;
                int key = idx >> 4, c = idx & 15;
                float4 k4 = kg[(size_t)key*(rs/4) + c];
                float4 v4 = vg[(size_t)key*(rs/4) + c];
                int sub = c >> 1;
                int eg  = (c & 1) * 4;               // e&7 base for this float4
                u32* kd = Kt + key*KSTR + sub;
                u32* vd = Vt + key*KSTR + sub;
                kd[(((eg+0)+key)&7)*8] = f2tf(k4.x);
                kd[(((eg+1)+key)&7)*8] = f2tf(k4.y);
                kd[(((eg+2)+key)&7)*8] = f2tf(k4.z);
                kd[(((eg+3)+key)&7)*8] = f2tf(k4.w);
                vd[(((eg+0)+key)&7)*8] = f2tf(v4.x);
                vd[(((eg+1)+key)&7)*8] = f2tf(v4.y);
                vd[(((eg+2)+key)&7)*8] = f2tf(v4.z);
                vd[(((eg+3)+key)&7)*8] = f2tf(v4.w);
            }
        }
        __syncthreads();

        const int jmax = (wlmax - nb) >> 3;  // chunks with any unmasked key

        // ---- fused per-8-key-chunk: QK -> softmax -> PV ----
        #pragma unroll
        for (int j=0;j<16;j++) if (j <= jmax) {
            // QK fragment vectors: 4x LDS.128
            const u32* kr = Kt + (8*j + gid)*KSTR;
            uint4 ka0 = *(const uint4*)(kr + gq0);
            uint4 ka1 = *(const uint4*)(kr + gq0 + 4);
            uint4 kb0 = *(const uint4*)(kr + gq1);
            uint4 kb1 = *(const uint4*)(kr + gq1 + 4);

            // 4 independent accumulator chains (hi x2, lo x2)
            float sa0[4]={0,0,0,0}, sa1[4]={0,0,0,0};
            float sb0[4]={0,0,0,0}, sb1[4]={0,0,0,0};
            MMA(sa0, qf[0][0],qf[0][1],qf[0][2],qf[0][3], ka0.x, kb0.x);
            MMA(sb0, ql[0][0],ql[0][1],ql[0][2],ql[0][3], ka0.x, kb0.x);
            MMA(sa1, qf[1][0],qf[1][1],qf[1][2],qf[1][3], ka0.y, kb0.y);
            MMA(sb1, ql[1][0],ql[1][1],ql[1][2],ql[1][3], ka0.y, kb0.y);
            MMA(sa0, qf[2][0],qf[2][1],qf[2][2],qf[2][3], ka0.z, kb0.z);
            MMA(sb0, ql[2][0],ql[2][1],ql[2][2],ql[2][3], ka0.z, kb0.z);
            MMA(sa1, qf[3][0],qf[3][1],qf[3][2],qf[3][3], ka0.w, kb0.w);
            MMA(sb1, ql[3][0],ql[3][1],ql[3][2],ql[3][3], ka0.w, kb0.w);
            MMA(sa0, qf[4][0],qf[4][1],qf[4][2],qf[4][3], ka1.x, kb1.x);
            MMA(sb0, ql[4][0],ql[4][1],ql[4][2],ql[4][3], ka1.x, kb1.x);
            MMA(sa1, qf[5][0],qf[5][1],qf[5][2],qf[5][3], ka1.y, kb1.y);
            MMA(sb1, ql[5][0],ql[5][1],ql[5][2],ql[5][3], ka1.y, kb1.y);
            MMA(sa0, qf[6][0],qf[6][1],qf[6][2],qf[6][3], ka1.z, kb1.z);
            MMA(sb0, ql[6][0],ql[6][1],ql[6][2],ql[6][3], ka1.z, kb1.z);
            MMA(sa1, qf[7][0],qf[7][1],qf[7][2],qf[7][3], ka1.w, kb1.w);
            MMA(sb1, ql[7][0],ql[7][1],ql[7][2],ql[7][3], ka1.w, kb1.w);

            // softmax (no max-sub; logits small) + tf32 P
            int c0 = nb + 8*j + 2*tig;
            int c1 = c0 + 1;
            float v0=(sa0[0]+sa1[0])+(sb0[0]+sb1[0]);
            float v1=(sa0[1]+sa1[1])+(sb0[1]+sb1[1]);
            float v2=(sa0[2]+sa1[2])+(sb0[2]+sb1[2]);
            float v3=(sa0[3]+sa1[3])+(sb0[3]+sb1[3]);
            if (rlo >= hist) {
                if (c0 == rlo) v0 = dlo;
                if (c1 == rlo) v1 = dlo;
                if (c0 == rhi) v2 = dhi;
                if (c1 == rhi) v3 = dhi;
            }
            float p0 = (c0 <= rlo) ? __expf(0.125f*v0) : 0.f;
            float p1 = (c1 <= rlo) ? __expf(0.125f*v1) : 0.f;
            float p2 = (c0 <= rhi) ? __expf(0.125f*v2) : 0.f;
            float p3 = (c1 <= rhi) ? __expf(0.125f*v3) : 0.f;
            sumlo += p0 + p1; sumhi += p2 + p3;
            float w0 = __uint_as_float(f2tf(p0));
            float w1 = __uint_as_float(f2tf(p1));
            float w2 = __uint_as_float(f2tf(p2));
            float w3 = __uint_as_float(f2tf(p3));

            // quad-shfl C-frag -> A-frag permute
            float t0 = __shfl_sync(0xffffffffu, w0, src0);
            float t1 = __shfl_sync(0xffffffffu, w1, src0);
            float t2 = __shfl_sync(0xffffffffu, w0, src1);
            float t3 = __shfl_sync(0xffffffffu, w1, src1);
            float t4 = __shfl_sync(0xffffffffu, w2, src0);
            float t5 = __shfl_sync(0xffffffffu, w3, src0);
            float t6 = __shfl_sync(0xffffffffu, w2, src1);
            float t7 = __shfl_sync(0xffffffffu, w3, src1);
            u32 a0 = __float_as_uint(oddm ? t1 : t0);
            u32 a2 = __float_as_uint(oddm ? t3 : t2);
            u32 a1 = __float_as_uint(oddm ? t5 : t4);
            u32 a3 = __float_as_uint(oddm ? t7 : t6);

            // PV fragment vectors: 4x LDS.128
            const u32* vr0 = Vt + (8*j + tig)*KSTR + gvA;
            const u32* vr1 = Vt + (8*j + tig + 4)*KSTR + gvB;
            uint4 va0 = *(const uint4*)(vr0);
            uint4 va1 = *(const uint4*)(vr0 + 4);
            uint4 vb0 = *(const uint4*)(vr1);
            uint4 vb1 = *(const uint4*)(vr1 + 4);

            MMA(o[0], a0,a1,a2,a3, va0.x, vb0.x);
            MMA(o[1], a0,a1,a2,a3, va0.y, vb0.y);
            MMA(o[2], a0,a1,a2,a3, va0.z, vb0.z);
            MMA(o[3], a0,a1,a2,a3, va0.w, vb0.w);
            MMA(o[4], a0,a1,a2,a3, va1.x, vb1.x);
            MMA(o[5], a0,a1,a2,a3, va1.y, vb1.y);
            MMA(o[6], a0,a1,a2,a3, va1.z, vb1.z);
            MMA(o[7], a0,a1,a2,a3, va1.w, vb1.w);
        }
    }

    // ---- complete row sums across the 4-lane quad ----
    sumlo += __shfl_xor_sync(0xffffffffu, sumlo, 1);
    sumlo += __shfl_xor_sync(0xffffffffu, sumlo, 2);
    sumhi += __shfl_xor_sync(0xffffffffu, sumhi, 1);
    sumhi += __shfl_xor_sync(0xffffffffu, sumhi, 2);
    const float ilo = 1.f/sumlo, ihi = 1.f/sumhi;

    // ---- epilogue ----
    float* out_lo = Out + base + (size_t)rlo*rs;
    float* out_hi = Out + base + (size_t)rhi*rs;
    if (rlo >= hist) {
        const float pdlo = __expf(0.125f*dlo) * ilo;
        const float pdhi = __expf(0.125f*dhi) * ihi;
        const float* vlo = V  + base + (size_t)rlo*rs;
        const float* vhi = V  + base + (size_t)rhi*rs;
        const float* dvlo = Vd + base + (size_t)rlo*rs;
        const float* dvhi = Vd + base + (size_t)rhi*rs;
        #pragma unroll
        for (int j2=0;j2<8;j2++){
            int col = 8*j2 + 2*tig;
            float2 vl = *(const float2*)(vlo+col), dl = *(const float2*)(dvlo+col);
            float2 vh = *(const float2*)(vhi+col), dh = *(const float2*)(dvhi+col);
            float2 ol, oh;
            ol.x = o[j2][0]*ilo + pdlo*(dl.x - vl.x);
            ol.y = o[j2][1]*ilo + pdlo*(dl.y - vl.y);
            oh.x = o[j2][2]*ihi + pdhi*(dh.x - vh.x);
            oh.y = o[j2][3]*ihi + pdhi*(dh.y - vh.y);
            *(float2*)(out_lo+col) = ol;
            *(float2*)(out_hi+col) = oh;
        }
    } else {
        #pragma unroll
        for (int j2=0;j2<8;j2++){
            int col = 8*j2 + 2*tig;
            *(float2*)(out_lo+col) = make_float2(o[j2][0]*ilo, o[j2][1]*ilo);
            *(float2*)(out_hi+col) = make_float2(o[j2][2]*ihi, o[j2][3]*ihi);
        }
    }
}

extern "C" void kernel_launch(void* const* d_in, const int* in_sizes, int n_in,
                              void* d_out, int out_size) {
    const float* Q  = (const float*)d_in[0];
    const float* K  = (const float*)d_in[1];
    const float* V  = (const float*)d_in[2];
    const float* Qd = (const float*)d_in[3];
    const float* Kd = (const float*)d_in[4];
    const float* Vd = (const float*)d_in[5];
    const int* histp = (const int*)d_in[7];
    cudaFuncSetAttribute(ffcca_mma, cudaFuncAttributeMaxDynamicSharedMemorySize, SMEM_TOTAL);
    dim3 grid(L_ / BQ, B_ * H_);
    ffcca_mma<<<grid, NTH, SMEM_TOTAL>>>(Q, K, V, Qd, Kd, Vd, histp, (float*)d_out);
}

// round 10
// speedup vs baseline: 1.3568x; 1.3568x over previous
#include <cuda_runtime.h>
#include <cstdint>

// FullFixedTimeCausalConstructiveAttention — mma.sync m16n8k8 tf32 flash attn.
// Round 8: round-6 structure (strided smem, fused per-8-key chunk) with
// (a) Q-residual dropped (8 QK MMAs/chunk; error budget allows it),
// (b) BK=64 + __launch_bounds__(128,4) -> 16 warps/SM.

#define B_ 8
#define L_ 1024
#define H_ 8
#define E_ 64
#define BQ 64
#define BK 64
#define NTH 128
#define KSTR 68     // K tile row stride (u32) — bank-conflict-free B frags
#define VSTR 72     // V tile row stride (u32)

#define SM_DIAG 0
#define SM_K 256
#define SM_V (SM_K + BK*KSTR*4)
#define SMEM_TOTAL (SM_V + BK*VSTR*4)

typedef unsigned u32;

__device__ __forceinline__ u32 f2tf(float x){ u32 u;
  asm("cvt.rna.tf32.f32 %0, %1;":"=r"(u):"f"(x)); return u; }

#define MMA(d, a0,a1,a2,a3, b0,b1) \
  asm volatile("mma.sync.aligned.m16n8k8.row.col.f32.tf32.tf32.f32 " \
    "{%0,%1,%2,%3}, {%4,%5,%6,%7}, {%8,%9}, {%0,%1,%2,%3};" \
    : "+f"((d)[0]),"+f"((d)[1]),"+f"((d)[2]),"+f"((d)[3]) \
    : "r"(a0),"r"(a1),"r"(a2),"r"(a3), "r"(b0),"r"(b1))

__global__ void __launch_bounds__(NTH, 4)
ffcca_mma(const float* __restrict__ Q, const float* __restrict__ K,
          const float* __restrict__ V, const float* __restrict__ Qd,
          const float* __restrict__ Kd, const float* __restrict__ Vd,
          const int* __restrict__ histp, float* __restrict__ Out)
{
    extern __shared__ char smem[];
    float* sdiag = (float*)(smem + SM_DIAG);
    u32* Kt = (u32*)(smem + SM_K);
    u32* Vt = (u32*)(smem + SM_V);

    const int hist = *histp;                 // 512
    const int t = threadIdx.x;
    const int w = t >> 5, lane = t & 31;
    const int gid = lane >> 2, tig = lane & 3;
    const int qt = blockIdx.x, bh = blockIdx.y;
    const int b = bh >> 3, h = bh & 7;
    const int m0 = qt * BQ;
    const size_t rs = (size_t)H_ * E_;       // 512 floats per l
    const size_t base = (size_t)b * L_ * rs + (size_t)h * E_;

    const int rlo = m0 + w*16 + gid;         // this lane's two rows
    const int rhi = rlo + 8;

    // ---- exact fp32 diagonal scores for rows m0..m0+63 ----
    if (t < BQ) {
        int row = m0 + t;
        const float* qs = (row < hist) ? Q : Qd;
        const float4* qr = (const float4*)(qs + base + (size_t)row*rs);
        const float4* kr = (const float4*)(Kd + base + (size_t)row*rs);
        float a0=0,a1=0,a2=0,a3=0;
        #pragma unroll
        for (int c=0;c<16;c++){ float4 q4=qr[c], k4=kr[c];
            a0+=q4.x*k4.x; a1+=q4.y*k4.y; a2+=q4.z*k4.z; a3+=q4.w*k4.w; }
        sdiag[t] = (a0+a1)+(a2+a3);
    }

    // ---- Q fragments (tf32) for this warp's 16 rows ----
    u32 qf[8][4];
    {
        const float* qs = (rlo < hist) ? Q : Qd;   // 16-row block is hist-uniform
        const float* qlo = qs + base + (size_t)rlo*rs;
        const float* qhi = qs + base + (size_t)rhi*rs;
        #pragma unroll
        for (int s=0;s<8;s++){
            qf[s][0]=f2tf(qlo[8*s+tig]);
            qf[s][1]=f2tf(qhi[8*s+tig]);
            qf[s][2]=f2tf(qlo[8*s+tig+4]);
            qf[s][3]=f2tf(qhi[8*s+tig+4]);
        }
    }

    __syncthreads();                         // sdiag visible
    const float dlo = sdiag[rlo - m0];
    const float dhi = sdiag[rhi - m0];

    float o[8][4];
    #pragma unroll
    for (int j=0;j<8;j++){ o[j][0]=o[j][1]=o[j][2]=o[j][3]=0.f; }
    float sumlo=0.f, sumhi=0.f;

    const int wlmax = (m0 + w*16) + 15;      // warp's max query row
    const int ntiles = (m0 + BQ) / BK;       // = qt+1
    const int src0 = (lane & ~3) | (tig >> 1);
    const int src1 = src0 + 2;
    const bool oddm = (tig & 1) != 0;

    for (int nt = 0; nt < ntiles; nt++) {
        const int nb = nt * BK;
        __syncthreads();                     // previous tile fully consumed
        // ---- cooperative K/V tile load (tf32) ----
        {
            const float4* kg = (const float4*)(K + base + (size_t)nb*rs);
            const float4* vg = (const float4*)(V + base + (size_t)nb*rs);
            #pragma unroll
            for (int i=0;i<8;i++){
                int idx = t + i*NTH;
                int key = idx >> 4, c = idx & 15;
                float4 k4 = kg[(size_t)key*(rs/4) + c];
                float4 v4 = vg[(size_t)key*(rs/4) + c];
                uint4 ku = make_uint4(f2tf(k4.x),f2tf(k4.y),f2tf(k4.z),f2tf(k4.w));
                uint4 vu = make_uint4(f2tf(v4.x),f2tf(v4.y),f2tf(v4.z),f2tf(v4.w));
                *(uint4*)(Kt + key*KSTR + 4*c) = ku;
                *(uint4*)(Vt + key*VSTR + 4*c) = vu;
            }
        }
        __syncthreads();

        const int jmax = (wlmax - nb) >> 3;  // chunks with any unmasked key

        // ---- fused per-8-key-chunk: QK -> softmax -> PV ----
        #pragma unroll
        for (int j=0;j<8;j++) if (j <= jmax) {
            // QK: two independent accumulator chains
            float sa[4] = {0.f,0.f,0.f,0.f};
            float sb[4] = {0.f,0.f,0.f,0.f};
            const u32* kr = Kt + (8*j + gid)*KSTR;
            #pragma unroll
            for (int st=0;st<8;st+=2){
                u32 b0 = kr[8*st + tig],     b1 = kr[8*st + tig + 4];
                u32 b2 = kr[8*st + 8 + tig], b3 = kr[8*st + 8 + tig + 4];
                MMA(sa, qf[st][0],qf[st][1],qf[st][2],qf[st][3], b0,b1);
                MMA(sb, qf[st+1][0],qf[st+1][1],qf[st+1][2],qf[st+1][3], b2,b3);
            }

            // softmax (no max-sub; logits small) + tf32 P
            int c0 = nb + 8*j + 2*tig;
            int c1 = c0 + 1;
            float v0=sa[0]+sb[0], v1=sa[1]+sb[1], v2=sa[2]+sb[2], v3=sa[3]+sb[3];
            if (rlo >= hist) {
                if (c0 == rlo) v0 = dlo;
                if (c1 == rlo) v1 = dlo;
                if (c0 == rhi) v2 = dhi;
                if (c1 == rhi) v3 = dhi;
            }
            float p0 = (c0 <= rlo) ? __expf(0.125f*v0) : 0.f;
            float p1 = (c1 <= rlo) ? __expf(0.125f*v1) : 0.f;
            float p2 = (c0 <= rhi) ? __expf(0.125f*v2) : 0.f;
            float p3 = (c1 <= rhi) ? __expf(0.125f*v3) : 0.f;
            sumlo += p0 + p1; sumhi += p2 + p3;
            float w0 = __uint_as_float(f2tf(p0));
            float w1 = __uint_as_float(f2tf(p1));
            float w2 = __uint_as_float(f2tf(p2));
            float w3 = __uint_as_float(f2tf(p3));

            // quad-shfl C-frag -> A-frag permute
            float t0 = __shfl_sync(0xffffffffu, w0, src0);
            float t1 = __shfl_sync(0xffffffffu, w1, src0);
            float t2 = __shfl_sync(0xffffffffu, w0, src1);
            float t3 = __shfl_sync(0xffffffffu, w1, src1);
            float t4 = __shfl_sync(0xffffffffu, w2, src0);
            float t5 = __shfl_sync(0xffffffffu, w3, src0);
            float t6 = __shfl_sync(0xffffffffu, w2, src1);
            float t7 = __shfl_sync(0xffffffffu, w3, src1);
            u32 a0 = __float_as_uint(oddm ? t1 : t0);
            u32 a2 = __float_as_uint(oddm ? t3 : t2);
            u32 a1 = __float_as_uint(oddm ? t5 : t4);
            u32 a3 = __float_as_uint(oddm ? t7 : t6);

            // PV: O += P_chunk . V_chunk (8 independent accumulators)
            const u32* v0r = Vt + (8*j + tig)*VSTR;
            const u32* v1r = Vt + (8*j + tig + 4)*VSTR;
            #pragma unroll
            for (int j2=0;j2<8;j2++){
                u32 b0 = v0r[8*j2 + gid], b1 = v1r[8*j2 + gid];
                MMA(o[j2], a0,a1,a2,a3, b0,b1);
            }
        }
    }

    // ---- complete row sums across the 4-lane quad ----
    sumlo += __shfl_xor_sync(0xffffffffu, sumlo, 1);
    sumlo += __shfl_xor_sync(0xffffffffu, sumlo, 2);
    sumhi += __shfl_xor_sync(0xffffffffu, sumhi, 1);
    sumhi += __shfl_xor_sync(0xffffffffu, sumhi, 2);
    const float ilo = 1.f/sumlo, ihi = 1.f/sumhi;

    // ---- epilogue ----
    float* out_lo = Out + base + (size_t)rlo*rs;
    float* out_hi = Out + base + (size_t)rhi*rs;
    if (rlo >= hist) {
        const float pdlo = __expf(0.125f*dlo) * ilo;
        const float pdhi = __expf(0.125f*dhi) * ihi;
        const float* vlo = V  + base + (size_t)rlo*rs;
        const float* vhi = V  + base + (size_t)rhi*rs;
        const float* dvlo = Vd + base + (size_t)rlo*rs;
        const float* dvhi = Vd + base + (size_t)rhi*rs;
        #pragma unroll
        for (int j2=0;j2<8;j2++){
            int col = 8*j2 + 2*tig;
            float2 vl = *(const float2*)(vlo+col), dl = *(const float2*)(dvlo+col);
            float2 vh = *(const float2*)(vhi+col), dh = *(const float2*)(dvhi+col);
            float2 ol, oh;
            ol.x = o[j2][0]*ilo + pdlo*(dl.x - vl.x);
            ol.y = o[j2][1]*ilo + pdlo*(dl.y - vl.y);
            oh.x = o[j2][2]*ihi + pdhi*(dh.x - vh.x);
            oh.y = o[j2][3]*ihi + pdhi*(dh.y - vh.y);
            *(float2*)(out_lo+col) = ol;
            *(float2*)(out_hi+col) = oh;
        }
    } else {
        #pragma unroll
        for (int j2=0;j2<8;j2++){
            int col = 8*j2 + 2*tig;
            *(float2*)(out_lo+col) = make_float2(o[j2][0]*ilo, o[j2][1]*ilo);
            *(float2*)(out_hi+col) = make_float2(o[j2][2]*ihi, o[j2][3]*ihi);
        }
    }
}

extern "C" void kernel_launch(void* const* d_in, const int* in_sizes, int n_in,
                              void* d_out, int out_size) {
    const float* Q  = (const float*)d_in[0];
    const float* K  = (const float*)d_in[1];
    const float* V  = (const float*)d_in[2];
    const float* Qd = (const float*)d_in[3];
    const float* Kd = (const float*)d_in[4];
    const float* Vd = (const float*)d_in[5];
    const int* histp = (const int*)d_in[7];
    cudaFuncSetAttribute(ffcca_mma, cudaFuncAttributeMaxDynamicSharedMemorySize, SMEM_TOTAL);
    dim3 grid(L_ / BQ, B_ * H_);
    ffcca_mma<<<grid, NTH, SMEM_TOTAL>>>(Q, K, V, Qd, Kd, Vd, histp, (float*)d_out);
}

// round 11
// speedup vs baseline: 1.6587x; 1.2226x over previous
#include <cuda_runtime.h>
#include <cstdint>

// FullFixedTimeCausalConstructiveAttention — mma.sync m16n8k8 tf32 flash attn.
// Round 9: balanced causal scheduling. CTA bx processes q-tile (15-bx) then
// q-tile bx sequentially -> every CTA does exactly 17 k-tile iterations;
// grid 512 = one balanced wave at 4 CTAs/SM. exp via exp2f (1 FMUL + MUFU).

#define B_ 8
#define L_ 1024
#define H_ 8
#define E_ 64
#define BQ 64
#define BK 64
#define NTH 128
#define GRIDX (L_ / BQ / 2)   // 8
#define KSTR 68     // K tile row stride (u32) — bank-conflict-free B frags
#define VSTR 72     // V tile row stride (u32)

#define SM_DIAG 0
#define SM_K 256
#define SM_V (SM_K + BK*KSTR*4)
#define SMEM_TOTAL (SM_V + BK*VSTR*4)

#define C2 0.18033688f   // 0.125 * log2(e)

typedef unsigned u32;

__device__ __forceinline__ u32 f2tf(float x){ u32 u;
  asm("cvt.rna.tf32.f32 %0, %1;":"=r"(u):"f"(x)); return u; }

#define MMA(d, a0,a1,a2,a3, b0,b1) \
  asm volatile("mma.sync.aligned.m16n8k8.row.col.f32.tf32.tf32.f32 " \
    "{%0,%1,%2,%3}, {%4,%5,%6,%7}, {%8,%9}, {%0,%1,%2,%3};" \
    : "+f"((d)[0]),"+f"((d)[1]),"+f"((d)[2]),"+f"((d)[3]) \
    : "r"(a0),"r"(a1),"r"(a2),"r"(a3), "r"(b0),"r"(b1))

__global__ void __launch_bounds__(NTH, 4)
ffcca_mma(const float* __restrict__ Q, const float* __restrict__ K,
          const float* __restrict__ V, const float* __restrict__ Qd,
          const float* __restrict__ Kd, const float* __restrict__ Vd,
          const int* __restrict__ histp, float* __restrict__ Out)
{
    extern __shared__ char smem[];
    float* sdiag = (float*)(smem + SM_DIAG);
    u32* Kt = (u32*)(smem + SM_K);
    u32* Vt = (u32*)(smem + SM_V);

    const int hist = *histp;                 // 512
    const int t = threadIdx.x;
    const int w = t >> 5, lane = t & 31;
    const int gid = lane >> 2, tig = lane & 3;
    const int bx = blockIdx.x, bh = blockIdx.y;
    const int b = bh >> 3, h = bh & 7;
    const size_t rs = (size_t)H_ * E_;       // 512 floats per l
    const size_t base = (size_t)b * L_ * rs + (size_t)h * E_;

    const int src0 = (lane & ~3) | (tig >> 1);
    const int src1 = src0 + 2;
    const bool oddm = (tig & 1) != 0;

    #pragma unroll 1
    for (int ph = 0; ph < 2; ph++) {
        const int qt = ph ? bx : (2*GRIDX - 1 - bx);   // heavy tile first
        const int m0 = qt * BQ;
        const int rlo = m0 + w*16 + gid;     // this lane's two rows
        const int rhi = rlo + 8;

        // ---- exact fp32 diagonal scores for rows m0..m0+63 ----
        if (t < BQ) {
            int row = m0 + t;
            const float* qs = (row < hist) ? Q : Qd;
            const float4* qr = (const float4*)(qs + base + (size_t)row*rs);
            const float4* kr = (const float4*)(Kd + base + (size_t)row*rs);
            float a0=0,a1=0,a2=0,a3=0;
            #pragma unroll
            for (int c=0;c<16;c++){ float4 q4=qr[c], k4=kr[c];
                a0+=q4.x*k4.x; a1+=q4.y*k4.y; a2+=q4.z*k4.z; a3+=q4.w*k4.w; }
            sdiag[t] = (a0+a1)+(a2+a3);
        }

        // ---- Q fragments (tf32) for this warp's 16 rows ----
        u32 qf[8][4];
        {
            const float* qs = (rlo < hist) ? Q : Qd;   // 16-row block hist-uniform
            const float* qlo = qs + base + (size_t)rlo*rs;
            const float* qhi = qs + base + (size_t)rhi*rs;
            #pragma unroll
            for (int s=0;s<8;s++){
                qf[s][0]=f2tf(qlo[8*s+tig]);
                qf[s][1]=f2tf(qhi[8*s+tig]);
                qf[s][2]=f2tf(qlo[8*s+tig+4]);
                qf[s][3]=f2tf(qhi[8*s+tig+4]);
            }
        }

        __syncthreads();                     // sdiag visible (also joins phases)
        const float dlo = sdiag[rlo - m0];
        const float dhi = sdiag[rhi - m0];

        float o[8][4];
        #pragma unroll
        for (int j=0;j<8;j++){ o[j][0]=o[j][1]=o[j][2]=o[j][3]=0.f; }
        float sumlo=0.f, sumhi=0.f;

        const int wlmax = (m0 + w*16) + 15;  // warp's max query row
        const int ntiles = qt + 1;

        #pragma unroll 1
        for (int nt = 0; nt < ntiles; nt++) {
            const int nb = nt * BK;
            __syncthreads();                 // previous tile fully consumed
            // ---- cooperative K/V tile load (tf32) ----
            {
                const float4* kg = (const float4*)(K + base + (size_t)nb*rs);
                const float4* vg = (const float4*)(V + base + (size_t)nb*rs);
                #pragma unroll
                for (int i=0;i<8;i++){
                    int idx = t + i*NTH;
                    int key = idx >> 4, c = idx & 15;
                    float4 k4 = kg[(size_t)key*(rs/4) + c];
                    float4 v4 = vg[(size_t)key*(rs/4) + c];
                    uint4 ku = make_uint4(f2tf(k4.x),f2tf(k4.y),f2tf(k4.z),f2tf(k4.w));
                    uint4 vu = make_uint4(f2tf(v4.x),f2tf(v4.y),f2tf(v4.z),f2tf(v4.w));
                    *(uint4*)(Kt + key*KSTR + 4*c) = ku;
                    *(uint4*)(Vt + key*VSTR + 4*c) = vu;
                }
            }
            __syncthreads();

            const int jmax = (wlmax - nb) >> 3;  // chunks with any unmasked key

            // ---- fused per-8-key-chunk: QK -> softmax -> PV ----
            #pragma unroll
            for (int j=0;j<8;j++) if (j <= jmax) {
                // QK: two independent accumulator chains
                float sa[4] = {0.f,0.f,0.f,0.f};
                float sb[4] = {0.f,0.f,0.f,0.f};
                const u32* kr = Kt + (8*j + gid)*KSTR;
                #pragma unroll
                for (int st=0;st<8;st+=2){
                    u32 b0 = kr[8*st + tig],     b1 = kr[8*st + tig + 4];
                    u32 b2 = kr[8*st + 8 + tig], b3 = kr[8*st + 8 + tig + 4];
                    MMA(sa, qf[st][0],qf[st][1],qf[st][2],qf[st][3], b0,b1);
                    MMA(sb, qf[st+1][0],qf[st+1][1],qf[st+1][2],qf[st+1][3], b2,b3);
                }

                // softmax (no max-sub; logits small), tf32 P
                int c0 = nb + 8*j + 2*tig;
                int c1 = c0 + 1;
                float v0=sa[0]+sb[0], v1=sa[1]+sb[1], v2=sa[2]+sb[2], v3=sa[3]+sb[3];
                if (rlo >= hist) {
                    if (c0 == rlo) v0 = dlo;
                    if (c1 == rlo) v1 = dlo;
                    if (c0 == rhi) v2 = dhi;
                    if (c1 == rhi) v3 = dhi;
                }
                float p0 = (c0 <= rlo) ? exp2f(C2*v0) : 0.f;
                float p1 = (c1 <= rlo) ? exp2f(C2*v1) : 0.f;
                float p2 = (c0 <= rhi) ? exp2f(C2*v2) : 0.f;
                float p3 = (c1 <= rhi) ? exp2f(C2*v3) : 0.f;
                sumlo += p0 + p1; sumhi += p2 + p3;
                float w0 = __uint_as_float(f2tf(p0));
                float w1 = __uint_as_float(f2tf(p1));
                float w2 = __uint_as_float(f2tf(p2));
                float w3 = __uint_as_float(f2tf(p3));

                // quad-shfl C-frag -> A-frag permute
                float t0 = __shfl_sync(0xffffffffu, w0, src0);
                float t1 = __shfl_sync(0xffffffffu, w1, src0);
                float t2 = __shfl_sync(0xffffffffu, w0, src1);
                float t3 = __shfl_sync(0xffffffffu, w1, src1);
                float t4 = __shfl_sync(0xffffffffu, w2, src0);
                float t5 = __shfl_sync(0xffffffffu, w3, src0);
                float t6 = __shfl_sync(0xffffffffu, w2, src1);
                float t7 = __shfl_sync(0xffffffffu, w3, src1);
                u32 a0 = __float_as_uint(oddm ? t1 : t0);
                u32 a2 = __float_as_uint(oddm ? t3 : t2);
                u32 a1 = __float_as_uint(oddm ? t5 : t4);
                u32 a3 = __float_as_uint(oddm ? t7 : t6);

                // PV: O += P_chunk . V_chunk (8 independent accumulators)
                const u32* v0r = Vt + (8*j + tig)*VSTR;
                const u32* v1r = Vt + (8*j + tig + 4)*VSTR;
                #pragma unroll
                for (int j2=0;j2<8;j2++){
                    u32 b0 = v0r[8*j2 + gid], b1 = v1r[8*j2 + gid];
                    MMA(o[j2], a0,a1,a2,a3, b0,b1);
                }
            }
        }

        // ---- complete row sums across the 4-lane quad ----
        sumlo += __shfl_xor_sync(0xffffffffu, sumlo, 1);
        sumlo += __shfl_xor_sync(0xffffffffu, sumlo, 2);
        sumhi += __shfl_xor_sync(0xffffffffu, sumhi, 1);
        sumhi += __shfl_xor_sync(0xffffffffu, sumhi, 2);
        const float ilo = 1.f/sumlo, ihi = 1.f/sumhi;

        // ---- epilogue ----
        float* out_lo = Out + base + (size_t)rlo*rs;
        float* out_hi = Out + base + (size_t)rhi*rs;
        if (rlo >= hist) {
            const float pdlo = exp2f(C2*dlo) * ilo;
            const float pdhi = exp2f(C2*dhi) * ihi;
            const float* vlo = V  + base + (size_t)rlo*rs;
            const float* vhi = V  + base + (size_t)rhi*rs;
            const float* dvlo = Vd + base + (size_t)rlo*rs;
            const float* dvhi = Vd + base + (size_t)rhi*rs;
            #pragma unroll
            for (int j2=0;j2<8;j2++){
                int col = 8*j2 + 2*tig;
                float2 vl = *(const float2*)(vlo+col), dl = *(const float2*)(dvlo+col);
                float2 vh = *(const float2*)(vhi+col), dh = *(const float2*)(dvhi+col);
                float2 ol, oh;
                ol.x = o[j2][0]*ilo + pdlo*(dl.x - vl.x);
                ol.y = o[j2][1]*ilo + pdlo*(dl.y - vl.y);
                oh.x = o[j2][2]*ihi + pdhi*(dh.x - vh.x);
                oh.y = o[j2][3]*ihi + pdhi*(dh.y - vh.y);
                *(float2*)(out_lo+col) = ol;
                *(float2*)(out_hi+col) = oh;
            }
        } else {
            #pragma unroll
            for (int j2=0;j2<8;j2++){
                int col = 8*j2 + 2*tig;
                *(float2*)(out_lo+col) = make_float2(o[j2][0]*ilo, o[j2][1]*ilo);
                *(float2*)(out_hi+col) = make_float2(o[j2][2]*ihi, o[j2][3]*ihi);
            }
        }
    }
}

extern "C" void kernel_launch(void* const* d_in, const int* in_sizes, int n_in,
                              void* d_out, int out_size) {
    const float* Q  = (const float*)d_in[0];
    const float* K  = (const float*)d_in[1];
    const float* V  = (const float*)d_in[2];
    const float* Qd = (const float*)d_in[3];
    const float* Kd = (const float*)d_in[4];
    const float* Vd = (const float*)d_in[5];
    const int* histp = (const int*)d_in[7];
    cudaFuncSetAttribute(ffcca_mma, cudaFuncAttributeMaxDynamicSharedMemorySize, SMEM_TOTAL);
    dim3 grid(GRIDX, B_ * H_);
    ffcca_mma<<<grid, NTH, SMEM_TOTAL>>>(Q, K, V, Qd, Kd, Vd, histp, (float*)d_out);
}

// round 12
// speedup vs baseline: 2.3254x; 1.4019x over previous
#include <cuda_runtime.h>
#include <cuda_fp16.h>
#include <cstdint>

// FullFixedTimeCausalConstructiveAttention — mma.sync m16n8k16 **fp16** flash
// attention. Same mantissa width as tf32 (10 bits, rna) but half the MMA count,
// half the fragment LDS, and NO shfl transpose: fp16 A-fragment k-coords per
// thread == S C-fragment n-coords, so P converts C->A with 4 cvt packs.
// Balanced two-phase causal scheduling (each CTA: q-tile 15-bx then bx).

#define B_ 8
#define L_ 1024
#define H_ 8
#define E_ 64
#define BQ 64
#define BK 64
#define NTH 128
#define GRIDX (L_ / BQ / 2)
#define KSTRW 36    // K tile row stride (u32 words) — QK frags conflict-free
#define VSTRW 36    // V tile row stride (u32 words) — PV frags conflict-free

#define SM_DIAG 0
#define SM_K 256
#define SM_V (SM_K + BK*KSTRW*4)
#define SMEM_TOTAL (SM_V + E_*VSTRW*4)

#define C2 0.18033688f   // 0.125 * log2(e)

typedef unsigned u32;

__device__ __forceinline__ u32 packh2(float lo, float hi){ u32 r;
  asm("cvt.rn.f16x2.f32 %0, %1, %2;" : "=r"(r) : "f"(hi), "f"(lo)); return r; }

#define MMAH(d, a0,a1,a2,a3, b0,b1) \
  asm volatile("mma.sync.aligned.m16n8k16.row.col.f32.f16.f16.f32 " \
    "{%0,%1,%2,%3}, {%4,%5,%6,%7}, {%8,%9}, {%0,%1,%2,%3};" \
    : "+f"((d)[0]),"+f"((d)[1]),"+f"((d)[2]),"+f"((d)[3]) \
    : "r"(a0),"r"(a1),"r"(a2),"r"(a3), "r"(b0),"r"(b1))

__global__ void __launch_bounds__(NTH, 4)
ffcca_mma(const float* __restrict__ Q, const float* __restrict__ K,
          const float* __restrict__ V, const float* __restrict__ Qd,
          const float* __restrict__ Kd, const float* __restrict__ Vd,
          const int* __restrict__ histp, float* __restrict__ Out)
{
    extern __shared__ char smem[];
    float* sdiag = (float*)(smem + SM_DIAG);
    u32* Kt = (u32*)(smem + SM_K);   // [key 0..63][dim-pair word 0..31] stride 36
    u32* Vt = (u32*)(smem + SM_V);   // [e 0..63][key-pair word 0..31]   stride 36

    const int hist = *histp;                 // 512
    const int t = threadIdx.x;
    const int w = t >> 5, lane = t & 31;
    const int gid = lane >> 2, tig = lane & 3;
    const int bx = blockIdx.x, bh = blockIdx.y;
    const int b = bh >> 3, h = bh & 7;
    const size_t rs = (size_t)H_ * E_;       // 512 floats per l
    const size_t base = (size_t)b * L_ * rs + (size_t)h * E_;

    const int klo = lane >> 2;               // V producer: key-low within warp
    const int cl  = lane & 3;

    #pragma unroll 1
    for (int ph = 0; ph < 2; ph++) {
        const int qt = ph ? bx : (2*GRIDX - 1 - bx);   // heavy tile first
        const int m0 = qt * BQ;
        const int rlo = m0 + w*16 + gid;     // this lane's two rows
        const int rhi = rlo + 8;

        // ---- exact fp32 diagonal scores for rows m0..m0+63 ----
        if (t < BQ) {
            int row = m0 + t;
            const float* qs = (row < hist) ? Q : Qd;
            const float4* qr = (const float4*)(qs + base + (size_t)row*rs);
            const float4* kr = (const float4*)(Kd + base + (size_t)row*rs);
            float a0=0,a1=0,a2=0,a3=0;
            #pragma unroll
            for (int c=0;c<16;c++){ float4 q4=qr[c], k4=kr[c];
                a0+=q4.x*k4.x; a1+=q4.y*k4.y; a2+=q4.z*k4.z; a3+=q4.w*k4.w; }
            sdiag[t] = (a0+a1)+(a2+a3);
        }

        // ---- Q fragments (fp16 pairs) for this warp's 16 rows ----
        u32 qf[4][4];
        {
            const float* qs = (rlo < hist) ? Q : Qd;   // 16-row block hist-uniform
            const float* qlo = qs + base + (size_t)rlo*rs;
            const float* qhi = qs + base + (size_t)rhi*rs;
            #pragma unroll
            for (int s=0;s<4;s++){
                float2 x0 = *(const float2*)(qlo + 16*s + 2*tig);
                float2 x1 = *(const float2*)(qhi + 16*s + 2*tig);
                float2 x2 = *(const float2*)(qlo + 16*s + 8 + 2*tig);
                float2 x3 = *(const float2*)(qhi + 16*s + 8 + 2*tig);
                qf[s][0] = packh2(x0.x, x0.y);
                qf[s][1] = packh2(x1.x, x1.y);
                qf[s][2] = packh2(x2.x, x2.y);
                qf[s][3] = packh2(x3.x, x3.y);
            }
        }

        __syncthreads();                     // sdiag visible (also joins phases)
        const float dlo = sdiag[rlo - m0];
        const float dhi = sdiag[rhi - m0];

        float o[8][4];
        #pragma unroll
        for (int j=0;j<8;j++){ o[j][0]=o[j][1]=o[j][2]=o[j][3]=0.f; }
        float sumlo=0.f, sumhi=0.f;

        const int wlmax = (m0 + w*16) + 15;  // warp's max query row
        const int ntiles = qt + 1;

        #pragma unroll 1
        for (int nt = 0; nt < ntiles; nt++) {
            const int nb = nt * BK;
            __syncthreads();                 // previous tile fully consumed
            // ---- K tile: natural fp16 rows [key][dim-pair] ----
            {
                const float4* kg = (const float4*)(K + base + (size_t)nb*rs);
                #pragma unroll
                for (int i=0;i<8;i++){
                    int idx = t + i*NTH;
                    int key = idx >> 4, c = idx & 15;
                    float4 k4 = kg[(size_t)key*(rs/4) + c];
                    u32 w0 = packh2(k4.x, k4.y);
                    u32 w1 = packh2(k4.z, k4.w);
                    *(uint2*)(Kt + key*KSTRW + 2*c) = make_uint2(w0, w1);
                }
            }
            // ---- V tile: key-pair packed [e][keypair] via shfl_xor(4) ----
            {
                const float4* vg = (const float4*)(V + base + (size_t)nb*rs);
                #pragma unroll
                for (int i=0;i<8;i++){
                    int oidx = (t >> 5) + 4*i;           // 0..31
                    int kh = oidx & 7, chh = oidx >> 3;
                    int key = 8*kh + klo;
                    int c   = 4*chh + cl;
                    float4 v4 = vg[(size_t)key*(rs/4) + c];
                    float px = __shfl_xor_sync(0xffffffffu, v4.x, 4);
                    float py = __shfl_xor_sync(0xffffffffu, v4.y, 4);
                    float pz = __shfl_xor_sync(0xffffffffu, v4.z, 4);
                    float pw = __shfl_xor_sync(0xffffffffu, v4.w, 4);
                    bool evenk = ((klo & 1) == 0);
                    int kp = key >> 1;
                    u32 w0 = evenk ? packh2(v4.x, px) : packh2(pz, v4.z);
                    u32 w1 = evenk ? packh2(v4.y, py) : packh2(pw, v4.w);
                    int e0 = 4*c + (evenk ? 0 : 2);
                    Vt[e0*VSTRW + kp]     = w0;
                    Vt[(e0+1)*VSTRW + kp] = w1;
                }
            }
            __syncthreads();

            const int jmax = (wlmax - nb) >> 4;  // 16-key chunks with work

            // ---- fused per-16-key chunk: QK -> softmax -> PV ----
            #pragma unroll
            for (int j=0;j<4;j++) if (j <= jmax) {
                // QK: two n8 groups, 4 k16 steps each (2 independent chains)
                const u32* kb0 = Kt + (16*j + gid)*KSTRW;
                const u32* kb1 = kb0 + 8*KSTRW;
                float cg0[4]={0.f,0.f,0.f,0.f}, cg1[4]={0.f,0.f,0.f,0.f};
                #pragma unroll
                for (int s=0;s<4;s++){
                    u32 b0 = kb0[8*s+tig], b1 = kb0[8*s+tig+4];
                    u32 d0 = kb1[8*s+tig], d1 = kb1[8*s+tig+4];
                    MMAH(cg0, qf[s][0],qf[s][1],qf[s][2],qf[s][3], b0,b1);
                    MMAH(cg1, qf[s][0],qf[s][1],qf[s][2],qf[s][3], d0,d1);
                }

                // softmax (no max-sub; logits small)
                const int kb = nb + 16*j;
                int c0 = kb + 2*tig, c1 = c0 + 1;     // group0 keys
                int c2 = c0 + 8,     c3 = c1 + 8;     // group1 keys
                float v00=cg0[0], v01=cg0[1], v02=cg0[2], v03=cg0[3];
                float v10=cg1[0], v11=cg1[1], v12=cg1[2], v13=cg1[3];
                if (rlo >= hist) {
                    if (c0 == rlo) v00 = dlo;
                    if (c1 == rlo) v01 = dlo;
                    if (c2 == rlo) v10 = dlo;
                    if (c3 == rlo) v11 = dlo;
                    if (c0 == rhi) v02 = dhi;
                    if (c1 == rhi) v03 = dhi;
                    if (c2 == rhi) v12 = dhi;
                    if (c3 == rhi) v13 = dhi;
                }
                float p00 = (c0 <= rlo) ? exp2f(C2*v00) : 0.f;
                float p01 = (c1 <= rlo) ? exp2f(C2*v01) : 0.f;
                float p02 = (c0 <= rhi) ? exp2f(C2*v02) : 0.f;
                float p03 = (c1 <= rhi) ? exp2f(C2*v03) : 0.f;
                float p10 = (c2 <= rlo) ? exp2f(C2*v10) : 0.f;
                float p11 = (c3 <= rlo) ? exp2f(C2*v11) : 0.f;
                float p12 = (c2 <= rhi) ? exp2f(C2*v12) : 0.f;
                float p13 = (c3 <= rhi) ? exp2f(C2*v13) : 0.f;
                sumlo += (p00 + p01) + (p10 + p11);
                sumhi += (p02 + p03) + (p12 + p13);

                // P: C-frag -> fp16 A-frag, no shfl needed
                u32 a0 = packh2(p00, p01);   // row gid,   k 2tig..+1
                u32 a1 = packh2(p02, p03);   // row gid+8, k 2tig..+1
                u32 a2 = packh2(p10, p11);   // row gid,   k 2tig+8..+9
                u32 a3 = packh2(p12, p13);   // row gid+8, k 2tig+8..+9

                // PV: 8 e-groups, independent accumulators
                const u32* vr = Vt + gid*VSTRW + 8*j + tig;
                #pragma unroll
                for (int ge=0; ge<8; ge++){
                    u32 b0 = vr[ge*8*VSTRW];
                    u32 b1 = vr[ge*8*VSTRW + 4];
                    MMAH(o[ge], a0,a1,a2,a3, b0,b1);
                }
            }
        }

        // ---- complete row sums across the 4-lane quad ----
        sumlo += __shfl_xor_sync(0xffffffffu, sumlo, 1);
        sumlo += __shfl_xor_sync(0xffffffffu, sumlo, 2);
        sumhi += __shfl_xor_sync(0xffffffffu, sumhi, 1);
        sumhi += __shfl_xor_sync(0xffffffffu, sumhi, 2);
        const float ilo = 1.f/sumlo, ihi = 1.f/sumhi;

        // ---- epilogue ----
        float* out_lo = Out + base + (size_t)rlo*rs;
        float* out_hi = Out + base + (size_t)rhi*rs;
        if (rlo >= hist) {
            const float pdlo = exp2f(C2*dlo) * ilo;
            const float pdhi = exp2f(C2*dhi) * ihi;
            const float* vlo = V  + base + (size_t)rlo*rs;
            const float* vhi = V  + base + (size_t)rhi*rs;
            const float* dvlo = Vd + base + (size_t)rlo*rs;
            const float* dvhi = Vd + base + (size_t)rhi*rs;
            #pragma unroll
            for (int ge=0;ge<8;ge++){
                int col = 8*ge + 2*tig;
                float2 vl = *(const float2*)(vlo+col), dl = *(const float2*)(dvlo+col);
                float2 vh = *(const float2*)(vhi+col), dh = *(const float2*)(dvhi+col);
                float2 ol, oh;
                ol.x = o[ge][0]*ilo + pdlo*(dl.x - vl.x);
                ol.y = o[ge][1]*ilo + pdlo*(dl.y - vl.y);
                oh.x = o[ge][2]*ihi + pdhi*(dh.x - vh.x);
                oh.y = o[ge][3]*ihi + pdhi*(dh.y - vh.y);
                *(float2*)(out_lo+col) = ol;
                *(float2*)(out_hi+col) = oh;
            }
        } else {
            #pragma unroll
            for (int ge=0;ge<8;ge++){
                int col = 8*ge + 2*tig;
                *(float2*)(out_lo+col) = make_float2(o[ge][0]*ilo, o[ge][1]*ilo);
                *(float2*)(out_hi+col) = make_float2(o[ge][2]*ihi, o[ge][3]*ihi);
            }
        }
    }
}

extern "C" void kernel_launch(void* const* d_in, const int* in_sizes, int n_in,
                              void* d_out, int out_size) {
    const float* Q  = (const float*)d_in[0];
    const float* K  = (const float*)d_in[1];
    const float* V  = (const float*)d_in[2];
    const float* Qd = (const float*)d_in[3];
    const float* Kd = (const float*)d_in[4];
    const float* Vd = (const float*)d_in[5];
    const int* histp = (const int*)d_in[7];
    cudaFuncSetAttribute(ffcca_mma, cudaFuncAttributeMaxDynamicSharedMemorySize, SMEM_TOTAL);
    dim3 grid(GRIDX, B_ * H_);
    ffcca_mma<<<grid, NTH, SMEM_TOTAL>>>(Q, K, V, Qd, Kd, Vd, histp, (float*)d_out);
}

// round 14
// speedup vs baseline: 2.3883x; 1.0271x over previous
#include <cuda_runtime.h>
#include <cuda_fp16.h>
#include <cstdint>

// FullFixedTimeCausalConstructiveAttention — fp16 m16n8k16 flash attention,
// round 12: K/V prepacked to fp16 in gmem (exact smem layouts), main kernel
// streams tiles with cp.async.cg into double-buffered smem. Balanced two-phase
// causal scheduling. Hot loop identical to round 11 (rel_err preserved).

#define B_ 8
#define L_ 1024
#define H_ 8
#define E_ 64
#define BQ 64
#define BK 64
#define NTH 128
#define GRIDX (L_ / BQ / 2)
#define KSTRW 36            // tile row stride (u32 words), conflict-free frags
#define KBUFW (BK*KSTRW)    // 2304 words = 9216 B per buffer

#define SM_DIAG 0
#define SM_K 256
#define SM_V (SM_K + 2*KBUFW*4)
#define SMEM_TOTAL (SM_V + 2*KBUFW*4)   // 37120 B

#define C2 0.18033688f      // 0.125 * log2(e)

typedef unsigned u32;

// prepacked fp16: g_Kh[bh][key][e] (word = e-pair), g_Vt[bh][e][keypair]
__device__ u32 g_Kh[(size_t)B_*H_*L_*E_/2];
__device__ u32 g_Vt[(size_t)B_*H_*E_*L_/2];

__device__ __forceinline__ u32 packh2(float lo, float hi){ u32 r;
  asm("cvt.rn.f16x2.f32 %0, %1, %2;" : "=r"(r) : "f"(hi), "f"(lo)); return r; }

#define MMAH(d, a0,a1,a2,a3, b0,b1) \
  asm volatile("mma.sync.aligned.m16n8k16.row.col.f32.f16.f16.f32 " \
    "{%0,%1,%2,%3}, {%4,%5,%6,%7}, {%8,%9}, {%0,%1,%2,%3};" \
    : "+f"((d)[0]),"+f"((d)[1]),"+f"((d)[2]),"+f"((d)[3]) \
    : "r"(a0),"r"(a1),"r"(a2),"r"(a3), "r"(b0),"r"(b1))

#define CPA16(dst_u32addr, src_ptr) \
  asm volatile("cp.async.cg.shared.global [%0], [%1], 16;" \
    :: "r"(dst_u32addr), "l"(src_ptr) : "memory")
#define CPCOMMIT() asm volatile("cp.async.commit_group;" ::: "memory")
#define CPWAIT(n)  asm volatile("cp.async.wait_group %0;" :: "n"(n) : "memory")

// ---------------------------------------------------------------- prepack ----
__global__ void __launch_bounds__(NTH)
prepack(const float* __restrict__ K, const float* __restrict__ V)
{
    const int t = threadIdx.x;
    const int lane = t & 31;
    const int kb = blockIdx.x * 64;
    const int bh = blockIdx.y;
    const int b = bh >> 3, h = bh & 7;
    const size_t rs = (size_t)H_ * E_;
    const size_t base = (size_t)b * L_ * rs + (size_t)h * E_;

    // ---- K: [bh][key][e] fp16, natural order ----
    {
        int row = kb + (t >> 1);
        int half = (t & 1) * 32;             // e offset
        const float4* src = (const float4*)(K + base + (size_t)row*rs + half);
        u32* dst = g_Kh + ((size_t)bh*L_ + row)*32 + half/2;
        #pragma unroll
        for (int i = 0; i < 4; i++){
            float4 a = src[2*i], c = src[2*i+1];
            uint4 o4 = make_uint4(packh2(a.x,a.y), packh2(a.z,a.w),
                                  packh2(c.x,c.y), packh2(c.z,c.w));
            *(uint4*)(dst + 4*i) = o4;
        }
    }
    // ---- V: [bh][e][keypair] fp16 (key-pair packed via shfl_xor 4) ----
    {
        const int klo = lane >> 2;           // 0..7
        const int cl  = lane & 3;
        const float4* vg = (const float4*)(V + base);
        const size_t vbase = (size_t)bh * E_ * (L_/2);
        #pragma unroll
        for (int i = 0; i < 8; i++){
            int oidx = (t >> 5) + 4*i;       // 0..31
            int kh = oidx & 7, chh = oidx >> 3;
            int key = kb + 8*kh + klo;
            int c   = 4*chh + cl;
            float4 v4 = vg[(size_t)key*(rs/4) + c];
            float px = __shfl_xor_sync(0xffffffffu, v4.x, 4);
            float py = __shfl_xor_sync(0xffffffffu, v4.y, 4);
            float pz = __shfl_xor_sync(0xffffffffu, v4.z, 4);
            float pw = __shfl_xor_sync(0xffffffffu, v4.w, 4);
            bool evenk = ((klo & 1) == 0);
            int kp = key >> 1;
            u32 w0 = evenk ? packh2(v4.x, px) : packh2(pz, v4.z);
            u32 w1 = evenk ? packh2(v4.y, py) : packh2(pw, v4.w);
            int e0 = 4*c + (evenk ? 0 : 2);
            g_Vt[vbase + (size_t)e0*(L_/2) + kp]     = w0;
            g_Vt[vbase + (size_t)(e0+1)*(L_/2) + kp] = w1;
        }
    }
}

// ------------------------------------------------------------------- main ----
__global__ void __launch_bounds__(NTH, 4)
ffcca_mma(const float* __restrict__ Q, const float* __restrict__ V,
          const float* __restrict__ Qd, const float* __restrict__ Kd,
          const float* __restrict__ Vd, const int* __restrict__ histp,
          float* __restrict__ Out)
{
    extern __shared__ char smem[];
    float* sdiag = (float*)(smem + SM_DIAG);
    u32 sb; asm("{ .reg .u64 x; cvta.to.shared.u64 x, %1; cvt.u32.u64 %0, x; }"
                : "=r"(sb) : "l"(smem));

    const int hist = *histp;                 // 512
    const int t = threadIdx.x;
    const int w = t >> 5, lane = t & 31;
    const int gid = lane >> 2, tig = lane & 3;
    const int bx = blockIdx.x, bh = blockIdx.y;
    const int b = bh >> 3, h = bh & 7;
    const size_t rs = (size_t)H_ * E_;       // 512 floats per l
    const size_t base = (size_t)b * L_ * rs + (size_t)h * E_;

    const u32* KsrcB = g_Kh + (size_t)bh * L_ * 32;
    const u32* VsrcB = g_Vt + (size_t)bh * E_ * (L_/2);
    const int ldr = t >> 3, ldc = t & 7;     // tile-chunk role: row 0..15, chunk 0..7

    #pragma unroll 1
    for (int ph = 0; ph < 2; ph++) {
        const int qt = ph ? bx : (2*GRIDX - 1 - bx);   // heavy tile first
        const int m0 = qt * BQ;
        const int rlo = m0 + w*16 + gid;
        const int rhi = rlo + 8;

        // ---- exact fp32 diagonal scores for rows m0..m0+63 ----
        if (t < BQ) {
            int row = m0 + t;
            const float* qs = (row < hist) ? Q : Qd;
            const float4* qr = (const float4*)(qs + base + (size_t)row*rs);
            const float4* kr = (const float4*)(Kd + base + (size_t)row*rs);
            float a0=0,a1=0,a2=0,a3=0;
            #pragma unroll
            for (int c=0;c<16;c++){ float4 q4=qr[c], k4=kr[c];
                a0+=q4.x*k4.x; a1+=q4.y*k4.y; a2+=q4.z*k4.z; a3+=q4.w*k4.w; }
            sdiag[t] = (a0+a1)+(a2+a3);
        }

        // ---- Q fragments (fp16 pairs) for this warp's 16 rows ----
        u32 qf[4][4];
        {
            const float* qs = (rlo < hist) ? Q : Qd;
            const float* qlo = qs + base + (size_t)rlo*rs;
            const float* qhi = qs + base + (size_t)rhi*rs;
            #pragma unroll
            for (int s=0;s<4;s++){
                float2 x0 = *(const float2*)(qlo + 16*s + 2*tig);
                float2 x1 = *(const float2*)(qhi + 16*s + 2*tig);
                float2 x2 = *(const float2*)(qlo + 16*s + 8 + 2*tig);
                float2 x3 = *(const float2*)(qhi + 16*s + 8 + 2*tig);
                qf[s][0] = packh2(x0.x, x0.y);
                qf[s][1] = packh2(x1.x, x1.y);
                qf[s][2] = packh2(x2.x, x2.y);
                qf[s][3] = packh2(x3.x, x3.y);
            }
        }

        float o[8][4];
        #pragma unroll
        for (int j=0;j<8;j++){ o[j][0]=o[j][1]=o[j][2]=o[j][3]=0.f; }
        float sumlo=0.f, sumhi=0.f;

        const int wlmax = (m0 + w*16) + 15;
        const int ntiles = qt + 1;
        int cur = 0;

        // ---- prologue: issue tile 0 into buffer 0 ----
        {
            const u32* ks = KsrcB;           // nb = 0
            const u32* vs = VsrcB;
            #pragma unroll
            for (int i=0;i<4;i++){
                int r = ldr + i*16;          // 0..63
                u32 doff = (r*KSTRW + ldc*4) * 4;
                CPA16(sb + SM_K + doff, ks + (size_t)r*32 + ldc*4);
                CPA16(sb + SM_V + doff, vs + (size_t)r*(L_/2) + ldc*4);
            }
            CPCOMMIT();
        }
        __syncthreads();                     // sdiag visible
        const float dlo = sdiag[rlo - m0];
        const float dhi = sdiag[rhi - m0];

        #pragma unroll 1
        for (int nt = 0; nt < ntiles; nt++) {
            if (nt + 1 < ntiles) {
                const int nb2 = (nt+1) * BK;
                const u32* ks = KsrcB + (size_t)nb2*32;
                const u32* vs = VsrcB + (nb2 >> 1);
                const u32 bo = (cur^1) * (KBUFW*4);
                #pragma unroll
                for (int i=0;i<4;i++){
                    int r = ldr + i*16;
                    u32 doff = (r*KSTRW + ldc*4) * 4;
                    CPA16(sb + SM_K + bo + doff, ks + (size_t)r*32 + ldc*4);
                    CPA16(sb + SM_V + bo + doff, vs + (size_t)r*(L_/2) + ldc*4);
                }
                CPCOMMIT();
                CPWAIT(1);                   // tile nt complete
            } else {
                CPWAIT(0);
            }
            __syncthreads();

            const u32* Kt = (const u32*)(smem + SM_K + cur*(KBUFW*4));
            const u32* Vt = (const u32*)(smem + SM_V + cur*(KBUFW*4));
            const int nb = nt * BK;
            const int jmax = (wlmax - nb) >> 4;

            // ---- fused per-16-key chunk: QK -> softmax -> PV ----
            #pragma unroll
            for (int j=0;j<4;j++) if (j <= jmax) {
                const u32* kb0 = Kt + (16*j + gid)*KSTRW;
                const u32* kb1 = kb0 + 8*KSTRW;
                float cg0[4]={0.f,0.f,0.f,0.f}, cg1[4]={0.f,0.f,0.f,0.f};
                #pragma unroll
                for (int s=0;s<4;s++){
                    u32 b0 = kb0[8*s+tig], b1 = kb0[8*s+tig+4];
                    u32 d0 = kb1[8*s+tig], d1 = kb1[8*s+tig+4];
                    MMAH(cg0, qf[s][0],qf[s][1],qf[s][2],qf[s][3], b0,b1);
                    MMAH(cg1, qf[s][0],qf[s][1],qf[s][2],qf[s][3], d0,d1);
                }

                const int kb = nb + 16*j;
                int c0 = kb + 2*tig, c1 = c0 + 1;
                int c2 = c0 + 8,     c3 = c1 + 8;
                float v00=cg0[0], v01=cg0[1], v02=cg0[2], v03=cg0[3];
                float v10=cg1[0], v11=cg1[1], v12=cg1[2], v13=cg1[3];
                if (rlo >= hist) {
                    if (c0 == rlo) v00 = dlo;
                    if (c1 == rlo) v01 = dlo;
                    if (c2 == rlo) v10 = dlo;
                    if (c3 == rlo) v11 = dlo;
                    if (c0 == rhi) v02 = dhi;
                    if (c1 == rhi) v03 = dhi;
                    if (c2 == rhi) v12 = dhi;
                    if (c3 == rhi) v13 = dhi;
                }
                float p00 = (c0 <= rlo) ? exp2f(C2*v00) : 0.f;
                float p01 = (c1 <= rlo) ? exp2f(C2*v01) : 0.f;
                float p02 = (c0 <= rhi) ? exp2f(C2*v02) : 0.f;
                float p03 = (c1 <= rhi) ? exp2f(C2*v03) : 0.f;
                float p10 = (c2 <= rlo) ? exp2f(C2*v10) : 0.f;
                float p11 = (c3 <= rlo) ? exp2f(C2*v11) : 0.f;
                float p12 = (c2 <= rhi) ? exp2f(C2*v12) : 0.f;
                float p13 = (c3 <= rhi) ? exp2f(C2*v13) : 0.f;
                sumlo += (p00 + p01) + (p10 + p11);
                sumhi += (p02 + p03) + (p12 + p13);

                u32 a0 = packh2(p00, p01);
                u32 a1 = packh2(p02, p03);
                u32 a2 = packh2(p10, p11);
                u32 a3 = packh2(p12, p13);

                const u32* vr = Vt + gid*KSTRW + 8*j + tig;
                #pragma unroll
                for (int ge=0; ge<8; ge++){
                    u32 b0 = vr[ge*8*KSTRW];
                    u32 b1 = vr[ge*8*KSTRW + 4];
                    MMAH(o[ge], a0,a1,a2,a3, b0,b1);
                }
            }
            __syncthreads();                 // buffer cur free for reuse
            cur ^= 1;
        }

        // ---- complete row sums across the 4-lane quad ----
        sumlo += __shfl_xor_sync(0xffffffffu, sumlo, 1);
        sumlo += __shfl_xor_sync(0xffffffffu, sumlo, 2);
        sumhi += __shfl_xor_sync(0xffffffffu, sumhi, 1);
        sumhi += __shfl_xor_sync(0xffffffffu, sumhi, 2);
        const float ilo = 1.f/sumlo, ihi = 1.f/sumhi;

        // ---- epilogue ----
        float* out_lo = Out + base + (size_t)rlo*rs;
        float* out_hi = Out + base + (size_t)rhi*rs;
        if (rlo >= hist) {
            const float pdlo = exp2f(C2*dlo) * ilo;
            const float pdhi = exp2f(C2*dhi) * ihi;
            const float* vlo = V  + base + (size_t)rlo*rs;
            const float* vhi = V  + base + (size_t)rhi*rs;
            const float* dvlo = Vd + base + (size_t)rlo*rs;
            const float* dvhi = Vd + base + (size_t)rhi*rs;
            #pragma unroll
            for (int ge=0;ge<8;ge++){
                int col = 8*ge + 2*tig;
                float2 vl = *(const float2*)(vlo+col), dl = *(const float2*)(dvlo+col);
                float2 vh = *(const float2*)(vhi+col), dh = *(const float2*)(dvhi+col);
                float2 ol, oh;
                ol.x = o[ge][0]*ilo + pdlo*(dl.x - vl.x);
                ol.y = o[ge][1]*ilo + pdlo*(dl.y - vl.y);
                oh.x = o[ge][2]*ihi + pdhi*(dh.x - vh.x);
                oh.y = o[ge][3]*ihi + pdhi*(dh.y - vh.y);
                *(float2*)(out_lo+col) = ol;
                *(float2*)(out_hi+col) = oh;
            }
        } else {
            #pragma unroll
            for (int ge=0;ge<8;ge++){
                int col = 8*ge + 2*tig;
                *(float2*)(out_lo+col) = make_float2(o[ge][0]*ilo, o[ge][1]*ilo);
                *(float2*)(out_hi+col) = make_float2(o[ge][2]*ihi, o[ge][3]*ihi);
            }
        }
        __syncthreads();                     // phase boundary (sdiag reuse)
    }
}

extern "C" void kernel_launch(void* const* d_in, const int* in_sizes, int n_in,
                              void* d_out, int out_size) {
    const float* Q  = (const float*)d_in[0];
    const float* K  = (const float*)d_in[1];
    const float* V  = (const float*)d_in[2];
    const float* Qd = (const float*)d_in[3];
    const float* Kd = (const float*)d_in[4];
    const float* Vd = (const float*)d_in[5];
    const int* histp = (const int*)d_in[7];
    dim3 pg(L_/64, B_ * H_);
    prepack<<<pg, NTH>>>(K, V);
    cudaFuncSetAttribute(ffcca_mma, cudaFuncAttributeMaxDynamicSharedMemorySize, SMEM_TOTAL);
    dim3 grid(GRIDX, B_ * H_);
    ffcca_mma<<<grid, NTH, SMEM_TOTAL>>>(Q, V, Qd, Kd, Vd, histp, (float*)d_out);
}

// round 15
// speedup vs baseline: 2.6288x; 1.1007x over previous
#include <cuda_runtime.h>
#include <cuda_fp16.h>
#include <cstdint>

// FullFixedTimeCausalConstructiveAttention — fp16 m16n8k16 flash attention.
// Round 14: (a) clean/diagonal chunk split — masking ALU runs in exactly ONE
// 16-key chunk per warp per phase, all other chunks are branch-free;
// (b) softmax scale folded into Q fragments (scores emerge in log2 domain,
// exp2f directly). Prepacked fp16 K/V + cp.async double buffering retained.

#define B_ 8
#define L_ 1024
#define H_ 8
#define E_ 64
#define BQ 64
#define BK 64
#define NTH 128
#define GRIDX (L_ / BQ / 2)
#define KSTRW 36            // tile row stride (u32 words), conflict-free frags
#define KBUFW (BK*KSTRW)    // words per buffer

#define SM_DIAG 0
#define SM_K 256
#define SM_V (SM_K + 2*KBUFW*4)
#define SMEM_TOTAL (SM_V + 2*KBUFW*4)   // 37120 B

#define C2 0.18033688f      // 0.125 * log2(e)

typedef unsigned u32;

// prepacked fp16: g_Kh[bh][key][e] (word = e-pair), g_Vt[bh][e][keypair]
__device__ u32 g_Kh[(size_t)B_*H_*L_*E_/2];
__device__ u32 g_Vt[(size_t)B_*H_*E_*L_/2];

__device__ __forceinline__ u32 packh2(float lo, float hi){ u32 r;
  asm("cvt.rn.f16x2.f32 %0, %1, %2;" : "=r"(r) : "f"(hi), "f"(lo)); return r; }

#define MMAH(d, a0,a1,a2,a3, b0,b1) \
  asm volatile("mma.sync.aligned.m16n8k16.row.col.f32.f16.f16.f32 " \
    "{%0,%1,%2,%3}, {%4,%5,%6,%7}, {%8,%9}, {%0,%1,%2,%3};" \
    : "+f"((d)[0]),"+f"((d)[1]),"+f"((d)[2]),"+f"((d)[3]) \
    : "r"(a0),"r"(a1),"r"(a2),"r"(a3), "r"(b0),"r"(b1))

#define CPA16(dst_u32addr, src_ptr) \
  asm volatile("cp.async.cg.shared.global [%0], [%1], 16;" \
    :: "r"(dst_u32addr), "l"(src_ptr) : "memory")
#define CPCOMMIT() asm volatile("cp.async.commit_group;" ::: "memory")
#define CPWAIT(n)  asm volatile("cp.async.wait_group %0;" :: "n"(n) : "memory")

// ---------------------------------------------------------------- prepack ----
__global__ void __launch_bounds__(NTH)
prepack(const float* __restrict__ K, const float* __restrict__ V)
{
    const int t = threadIdx.x;
    const int lane = t & 31;
    const int kb = blockIdx.x * 64;
    const int bh = blockIdx.y;
    const int b = bh >> 3, h = bh & 7;
    const size_t rs = (size_t)H_ * E_;
    const size_t base = (size_t)b * L_ * rs + (size_t)h * E_;

    // ---- K: [bh][key][e] fp16, natural order ----
    {
        int row = kb + (t >> 1);
        int half = (t & 1) * 32;
        const float4* src = (const float4*)(K + base + (size_t)row*rs + half);
        u32* dst = g_Kh + ((size_t)bh*L_ + row)*32 + half/2;
        #pragma unroll
        for (int i = 0; i < 4; i++){
            float4 a = src[2*i], c = src[2*i+1];
            uint4 o4 = make_uint4(packh2(a.x,a.y), packh2(a.z,a.w),
                                  packh2(c.x,c.y), packh2(c.z,c.w));
            *(uint4*)(dst + 4*i) = o4;
        }
    }
    // ---- V: [bh][e][keypair] fp16 (key-pair packed via shfl_xor 4) ----
    {
        const int klo = lane >> 2;
        const int cl  = lane & 3;
        const float4* vg = (const float4*)(V + base);
        const size_t vbase = (size_t)bh * E_ * (L_/2);
        #pragma unroll
        for (int i = 0; i < 8; i++){
            int oidx = (t >> 5) + 4*i;
            int kh = oidx & 7, chh = oidx >> 3;
            int key = kb + 8*kh + klo;
            int c   = 4*chh + cl;
            float4 v4 = vg[(size_t)key*(rs/4) + c];
            float px = __shfl_xor_sync(0xffffffffu, v4.x, 4);
            float py = __shfl_xor_sync(0xffffffffu, v4.y, 4);
            float pz = __shfl_xor_sync(0xffffffffu, v4.z, 4);
            float pw = __shfl_xor_sync(0xffffffffu, v4.w, 4);
            bool evenk = ((klo & 1) == 0);
            int kp = key >> 1;
            u32 w0 = evenk ? packh2(v4.x, px) : packh2(pz, v4.z);
            u32 w1 = evenk ? packh2(v4.y, py) : packh2(pw, v4.w);
            int e0 = 4*c + (evenk ? 0 : 2);
            g_Vt[vbase + (size_t)e0*(L_/2) + kp]     = w0;
            g_Vt[vbase + (size_t)(e0+1)*(L_/2) + kp] = w1;
        }
    }
}

// ------------------------------------------------------------------- main ----
__global__ void __launch_bounds__(NTH, 4)
ffcca_mma(const float* __restrict__ Q, const float* __restrict__ V,
          const float* __restrict__ Qd, const float* __restrict__ Kd,
          const float* __restrict__ Vd, const int* __restrict__ histp,
          float* __restrict__ Out)
{
    extern __shared__ char smem[];
    float* sdiag = (float*)(smem + SM_DIAG);
    u32 sb; asm("{ .reg .u64 x; cvta.to.shared.u64 x, %1; cvt.u32.u64 %0, x; }"
                : "=r"(sb) : "l"(smem));

    const int hist = *histp;                 // 512
    const int t = threadIdx.x;
    const int w = t >> 5, lane = t & 31;
    const int gid = lane >> 2, tig = lane & 3;
    const int bx = blockIdx.x, bh = blockIdx.y;
    const int b = bh >> 3, h = bh & 7;
    const size_t rs = (size_t)H_ * E_;
    const size_t base = (size_t)b * L_ * rs + (size_t)h * E_;

    const u32* KsrcB = g_Kh + (size_t)bh * L_ * 32;
    const u32* VsrcB = g_Vt + (size_t)bh * E_ * (L_/2);
    const int ldr = t >> 3, ldc = t & 7;

    #pragma unroll 1
    for (int ph = 0; ph < 2; ph++) {
        const int qt = ph ? bx : (2*GRIDX - 1 - bx);   // heavy tile first
        const int m0 = qt * BQ;
        const int wm0 = m0 + w*16;           // warp's first query row
        const int rlo = wm0 + gid;
        const int rhi = rlo + 8;

        // ---- exact fp32 diagonal scores for rows m0..m0+63 ----
        if (t < BQ) {
            int row = m0 + t;
            const float* qs = (row < hist) ? Q : Qd;
            const float4* qr = (const float4*)(qs + base + (size_t)row*rs);
            const float4* kr = (const float4*)(Kd + base + (size_t)row*rs);
            float a0=0,a1=0,a2=0,a3=0;
            #pragma unroll
            for (int c=0;c<16;c++){ float4 q4=qr[c], k4=kr[c];
                a0+=q4.x*k4.x; a1+=q4.y*k4.y; a2+=q4.z*k4.z; a3+=q4.w*k4.w; }
            sdiag[t] = (a0+a1)+(a2+a3);
        }

        // ---- Q fragments (fp16, PRE-SCALED by C2 -> scores in log2 domain) ----
        u32 qf[4][4];
        {
            const float* qs = (rlo < hist) ? Q : Qd;
            const float* qlo = qs + base + (size_t)rlo*rs;
            const float* qhi = qs + base + (size_t)rhi*rs;
            #pragma unroll
            for (int s=0;s<4;s++){
                float2 x0 = *(const float2*)(qlo + 16*s + 2*tig);
                float2 x1 = *(const float2*)(qhi + 16*s + 2*tig);
                float2 x2 = *(const float2*)(qlo + 16*s + 8 + 2*tig);
                float2 x3 = *(const float2*)(qhi + 16*s + 8 + 2*tig);
                qf[s][0] = packh2(C2*x0.x, C2*x0.y);
                qf[s][1] = packh2(C2*x1.x, C2*x1.y);
                qf[s][2] = packh2(C2*x2.x, C2*x2.y);
                qf[s][3] = packh2(C2*x3.x, C2*x3.y);
            }
        }

        float o[8][4];
        #pragma unroll
        for (int j=0;j<8;j++){ o[j][0]=o[j][1]=o[j][2]=o[j][3]=0.f; }
        float sumlo=0.f, sumhi=0.f;

        const int ntiles = qt + 1;
        int cur = 0;

        // ---- prologue: issue tile 0 into buffer 0 ----
        {
            #pragma unroll
            for (int i=0;i<4;i++){
                int r = ldr + i*16;
                u32 doff = (r*KSTRW + ldc*4) * 4;
                CPA16(sb + SM_K + doff, KsrcB + (size_t)r*32 + ldc*4);
                CPA16(sb + SM_V + doff, VsrcB + (size_t)r*(L_/2) + ldc*4);
            }
            CPCOMMIT();
        }
        __syncthreads();                     // sdiag visible
        const float dloS = C2 * sdiag[rlo - m0];   // log2-domain diag scores
        const float dhiS = C2 * sdiag[rhi - m0];

        #pragma unroll 1
        for (int nt = 0; nt < ntiles; nt++) {
            if (nt + 1 < ntiles) {
                const int nb2 = (nt+1) * BK;
                const u32* ks = KsrcB + (size_t)nb2*32;
                const u32* vs = VsrcB + (nb2 >> 1);
                const u32 bo = (cur^1) * (KBUFW*4);
                #pragma unroll
                for (int i=0;i<4;i++){
                    int r = ldr + i*16;
                    u32 doff = (r*KSTRW + ldc*4) * 4;
                    CPA16(sb + SM_K + bo + doff, ks + (size_t)r*32 + ldc*4);
                    CPA16(sb + SM_V + bo + doff, vs + (size_t)r*(L_/2) + ldc*4);
                }
                CPCOMMIT();
                CPWAIT(1);
            } else {
                CPWAIT(0);
            }
            __syncthreads();

            const u32* Kt = (const u32*)(smem + SM_K + cur*(KBUFW*4));
            const u32* Vt = (const u32*)(smem + SM_V + cur*(KBUFW*4));
            const int nb = nt * BK;
            const int dj = (wm0 - nb) >> 4;  // diag chunk idx; >=4 -> all clean
            const int ncln = (dj < 4) ? dj : 4;

            // ---- CLEAN chunks: no masking, no diag, exp2 direct ----
            #pragma unroll
            for (int j=0;j<4;j++) if (j < ncln) {
                const u32* kb0 = Kt + (16*j + gid)*KSTRW;
                const u32* kb1 = kb0 + 8*KSTRW;
                float cg0[4]={0.f,0.f,0.f,0.f}, cg1[4]={0.f,0.f,0.f,0.f};
                #pragma unroll
                for (int s=0;s<4;s++){
                    u32 b0 = kb0[8*s+tig], b1 = kb0[8*s+tig+4];
                    u32 d0 = kb1[8*s+tig], d1 = kb1[8*s+tig+4];
                    MMAH(cg0, qf[s][0],qf[s][1],qf[s][2],qf[s][3], b0,b1);
                    MMAH(cg1, qf[s][0],qf[s][1],qf[s][2],qf[s][3], d0,d1);
                }
                float p00 = exp2f(cg0[0]), p01 = exp2f(cg0[1]);
                float p02 = exp2f(cg0[2]), p03 = exp2f(cg0[3]);
                float p10 = exp2f(cg1[0]), p11 = exp2f(cg1[1]);
                float p12 = exp2f(cg1[2]), p13 = exp2f(cg1[3]);
                sumlo += (p00 + p01) + (p10 + p11);
                sumhi += (p02 + p03) + (p12 + p13);
                u32 a0 = packh2(p00, p01);
                u32 a1 = packh2(p02, p03);
                u32 a2 = packh2(p10, p11);
                u32 a3 = packh2(p12, p13);
                const u32* vr = Vt + gid*KSTRW + 8*j + tig;
                #pragma unroll
                for (int ge=0; ge<8; ge++){
                    u32 b0 = vr[ge*8*KSTRW];
                    u32 b1 = vr[ge*8*KSTRW + 4];
                    MMAH(o[ge], a0,a1,a2,a3, b0,b1);
                }
            }

            // ---- DIAGONAL chunk (at most one per tile; once per warp/phase) ----
            if (dj < 4) {
                const u32* kb0 = Kt + (16*dj + gid)*KSTRW;
                const u32* kb1 = kb0 + 8*KSTRW;
                float cg0[4]={0.f,0.f,0.f,0.f}, cg1[4]={0.f,0.f,0.f,0.f};
                #pragma unroll
                for (int s=0;s<4;s++){
                    u32 b0 = kb0[8*s+tig], b1 = kb0[8*s+tig+4];
                    u32 d0 = kb1[8*s+tig], d1 = kb1[8*s+tig+4];
                    MMAH(cg0, qf[s][0],qf[s][1],qf[s][2],qf[s][3], b0,b1);
                    MMAH(cg1, qf[s][0],qf[s][1],qf[s][2],qf[s][3], d0,d1);
                }
                const int kb = nb + 16*dj;   // == wm0
                int c0 = kb + 2*tig, c1 = c0 + 1;
                int c2 = c0 + 8,     c3 = c1 + 8;
                float v00=cg0[0], v01=cg0[1], v02=cg0[2], v03=cg0[3];
                float v10=cg1[0], v11=cg1[1], v12=cg1[2], v13=cg1[3];
                if (rlo >= hist) {
                    if (c0 == rlo) v00 = dloS;
                    if (c1 == rlo) v01 = dloS;
                    if (c2 == rlo) v10 = dloS;
                    if (c3 == rlo) v11 = dloS;
                    if (c0 == rhi) v02 = dhiS;
                    if (c1 == rhi) v03 = dhiS;
                    if (c2 == rhi) v12 = dhiS;
                    if (c3 == rhi) v13 = dhiS;
                }
                float p00 = (c0 <= rlo) ? exp2f(v00) : 0.f;
                float p01 = (c1 <= rlo) ? exp2f(v01) : 0.f;
                float p02 = (c0 <= rhi) ? exp2f(v02) : 0.f;
                float p03 = (c1 <= rhi) ? exp2f(v03) : 0.f;
                float p10 = (c2 <= rlo) ? exp2f(v10) : 0.f;
                float p11 = (c3 <= rlo) ? exp2f(v11) : 0.f;
                float p12 = (c2 <= rhi) ? exp2f(v12) : 0.f;
                float p13 = (c3 <= rhi) ? exp2f(v13) : 0.f;
                sumlo += (p00 + p01) + (p10 + p11);
                sumhi += (p02 + p03) + (p12 + p13);
                u32 a0 = packh2(p00, p01);
                u32 a1 = packh2(p02, p03);
                u32 a2 = packh2(p10, p11);
                u32 a3 = packh2(p12, p13);
                const u32* vr = Vt + gid*KSTRW + 8*dj + tig;
                #pragma unroll
                for (int ge=0; ge<8; ge++){
                    u32 b0 = vr[ge*8*KSTRW];
                    u32 b1 = vr[ge*8*KSTRW + 4];
                    MMAH(o[ge], a0,a1,a2,a3, b0,b1);
                }
            }
            __syncthreads();
            cur ^= 1;
        }

        // ---- complete row sums across the 4-lane quad ----
        sumlo += __shfl_xor_sync(0xffffffffu, sumlo, 1);
        sumlo += __shfl_xor_sync(0xffffffffu, sumlo, 2);
        sumhi += __shfl_xor_sync(0xffffffffu, sumhi, 1);
        sumhi += __shfl_xor_sync(0xffffffffu, sumhi, 2);
        const float ilo = 1.f/sumlo, ihi = 1.f/sumhi;

        // ---- epilogue ----
        float* out_lo = Out + base + (size_t)rlo*rs;
        float* out_hi = Out + base + (size_t)rhi*rs;
        if (rlo >= hist) {
            const float pdlo = exp2f(dloS) * ilo;
            const float pdhi = exp2f(dhiS) * ihi;
            const float* vlo = V  + base + (size_t)rlo*rs;
            const float* vhi = V  + base + (size_t)rhi*rs;
            const float* dvlo = Vd + base + (size_t)rlo*rs;
            const float* dvhi = Vd + base + (size_t)rhi*rs;
            #pragma unroll
            for (int ge=0;ge<8;ge++){
                int col = 8*ge + 2*tig;
                float2 vl = *(const float2*)(vlo+col), dl = *(const float2*)(dvlo+col);
                float2 vh = *(const float2*)(vhi+col), dh = *(const float2*)(dvhi+col);
                float2 ol, oh;
                ol.x = o[ge][0]*ilo + pdlo*(dl.x - vl.x);
                ol.y = o[ge][1]*ilo + pdlo*(dl.y - vl.y);
                oh.x = o[ge][2]*ihi + pdhi*(dh.x - vh.x);
                oh.y = o[ge][3]*ihi + pdhi*(dh.y - vh.y);
                *(float2*)(out_lo+col) = ol;
                *(float2*)(out_hi+col) = oh;
            }
        } else {
            #pragma unroll
            for (int ge=0;ge<8;ge++){
                int col = 8*ge + 2*tig;
                *(float2*)(out_lo+col) = make_float2(o[ge][0]*ilo, o[ge][1]*ilo);
                *(float2*)(out_hi+col) = make_float2(o[ge][2]*ihi, o[ge][3]*ihi);
            }
        }
        __syncthreads();                     // phase boundary (sdiag reuse)
    }
}

extern "C" void kernel_launch(void* const* d_in, const int* in_sizes, int n_in,
                              void* d_out, int out_size) {
    const float* Q  = (const float*)d_in[0];
    const float* K  = (const float*)d_in[1];
    const float* V  = (const float*)d_in[2];
    const float* Qd = (const float*)d_in[3];
    const float* Kd = (const float*)d_in[4];
    const float* Vd = (const float*)d_in[5];
    const int* histp = (const int*)d_in[7];
    dim3 pg(L_/64, B_ * H_);
    prepack<<<pg, NTH>>>(K, V);
    cudaFuncSetAttribute(ffcca_mma, cudaFuncAttributeMaxDynamicSharedMemorySize, SMEM_TOTAL);
    dim3 grid(GRIDX, B_ * H_);
    ffcca_mma<<<grid, NTH, SMEM_TOTAL>>>(Q, V, Qd, Kd, Vd, histp, (float*)d_out);
}

// round 16
// speedup vs baseline: 2.6951x; 1.0252x over previous
#include <cuda_runtime.h>
#include <cuda_fp16.h>
#include <cstdint>

// FullFixedTimeCausalConstructiveAttention — fp16 m16n8k16 flash attention.
// Round 15: (a) pair-interleaved K/V smem word layout -> every MMA B-fragment
// pair is ONE conflict-free LDS.64 (stride 40, phase-analyzed); (b) branch-free
// straight-line body for all-clean tiles (16 of 17 per warp-phase); (c) prepack
// V through an smem transpose -> coalesced 128B row writes.

#define B_ 8
#define L_ 1024
#define H_ 8
#define E_ 64
#define BQ 64
#define BK 64
#define NTH 128
#define GRIDX (L_ / BQ / 2)
#define KSTRW 40            // tile row stride (u32 words) — LDS.64 conflict-free
#define KBUFW (BK*KSTRW)

#define SM_DIAG 0
#define SM_K 256
#define SM_V (SM_K + 2*KBUFW*4)
#define SMEM_TOTAL (SM_V + 2*KBUFW*4)   // 41216 B

#define C2 0.18033688f      // 0.125 * log2(e)

typedef unsigned u32;

// prepacked fp16, pair-interleaved within 8-word groups:
// g_Kh[bh][key][32w], g_Vt[bh][e][512w]
__device__ u32 g_Kh[(size_t)B_*H_*L_*32];
__device__ u32 g_Vt[(size_t)B_*H_*E_*(L_/2)];

__device__ __forceinline__ u32 packh2(float lo, float hi){ u32 r;
  asm("cvt.rn.f16x2.f32 %0, %1, %2;" : "=r"(r) : "f"(hi), "f"(lo)); return r; }

#define MMAH(d, a0,a1,a2,a3, b0,b1) \
  asm volatile("mma.sync.aligned.m16n8k16.row.col.f32.f16.f16.f32 " \
    "{%0,%1,%2,%3}, {%4,%5,%6,%7}, {%8,%9}, {%0,%1,%2,%3};" \
    : "+f"((d)[0]),"+f"((d)[1]),"+f"((d)[2]),"+f"((d)[3]) \
    : "r"(a0),"r"(a1),"r"(a2),"r"(a3), "r"(b0),"r"(b1))

#define CPA16(dst_u32addr, src_ptr) \
  asm volatile("cp.async.cg.shared.global [%0], [%1], 16;" \
    :: "r"(dst_u32addr), "l"(src_ptr) : "memory")
#define CPCOMMIT() asm volatile("cp.async.commit_group;" ::: "memory")
#define CPWAIT(n)  asm volatile("cp.async.wait_group %0;" :: "n"(n) : "memory")

// ---------------------------------------------------------------- prepack ----
__global__ void __launch_bounds__(NTH)
prepack(const float* __restrict__ K, const float* __restrict__ V)
{
    __shared__ __half sh[64][66];            // V^T staging: [e][key] + pad
    const int t = threadIdx.x;
    const int kb = blockIdx.x * 64;
    const int bh = blockIdx.y;
    const int b = bh >> 3, h = bh & 7;
    const size_t rs = (size_t)H_ * E_;
    const size_t base = (size_t)b * L_ * rs + (size_t)h * E_;

    // ---- K: pair-interleaved rows [o0,o4,o1,o5,o2,o6,o3,o7] per 8w group ----
    {
        int row = kb + (t >> 1);
        int half = (t & 1) * 32;             // e offset (covers 2 groups)
        const float4* src = (const float4*)(K + base + (size_t)row*rs + half);
        u32* dst = g_Kh + ((size_t)bh*L_ + row)*32 + half/2;
        u32 wb[16];
        #pragma unroll
        for (int i = 0; i < 8; i++){
            float4 a = src[i];
            wb[2*i]   = packh2(a.x, a.y);
            wb[2*i+1] = packh2(a.z, a.w);
        }
        #pragma unroll
        for (int g = 0; g < 2; g++){
            u32* p = wb + 8*g;
            *(uint4*)(dst + 8*g)     = make_uint4(p[0], p[4], p[1], p[5]);
            *(uint4*)(dst + 8*g + 4) = make_uint4(p[2], p[6], p[3], p[7]);
        }
    }
    // ---- V: transpose to [e][key] in smem ----
    {
        int row = kb + (t >> 1);             // key
        int half = (t & 1) * 32;             // e offset
        const float4* src = (const float4*)(V + base + (size_t)row*rs + half);
        int key = row - kb;
        #pragma unroll
        for (int i = 0; i < 8; i++){
            float4 a = src[i];
            int e = half + 4*i;
            sh[e+0][key] = __float2half(a.x);
            sh[e+1][key] = __float2half(a.y);
            sh[e+2][key] = __float2half(a.z);
            sh[e+3][key] = __float2half(a.w);
        }
    }
    __syncthreads();
    // ---- V write: rows [e][keypair], pair-interleaved, coalesced 128B ----
    {
        int e  = t >> 1;
        int wh = (t & 1) * 16;               // output word offset within 32
        const u32* srow = (const u32*)&sh[e][0];
        u32* dst = g_Vt + ((size_t)bh*E_ + e)*(L_/2) + kb/2 + wh;
        u32 wb[16];
        #pragma unroll
        for (int wi = 0; wi < 16; wi++){
            int p = wi & 7;                  // position in 8-group (const)
            int w = (p & 1)*4 + (p >> 1);    // original keypair word
            int kp_local = wh + (wi & ~7) + w;
            wb[wi] = srow[kp_local];
        }
        #pragma unroll
        for (int i = 0; i < 4; i++)
            *(uint4*)(dst + 4*i) = make_uint4(wb[4*i], wb[4*i+1], wb[4*i+2], wb[4*i+3]);
    }
}

// --------------------------------------------------------------- chunk bodies
__device__ __forceinline__ void chunk_clean(
    const u32* Kt, const u32* Vt, const u32 qf[4][4], float o[8][4],
    float& sumlo, float& sumhi, int j, int gid, int tig)
{
    const u32* kb0 = Kt + (16*j + gid)*KSTRW;
    const u32* kb1 = kb0 + 8*KSTRW;
    float cg0[4]={0.f,0.f,0.f,0.f}, cg1[4]={0.f,0.f,0.f,0.f};
    #pragma unroll
    for (int s=0;s<4;s++){
        uint2 bb = *(const uint2*)(kb0 + 8*s + 2*tig);
        uint2 dd = *(const uint2*)(kb1 + 8*s + 2*tig);
        MMAH(cg0, qf[s][0],qf[s][1],qf[s][2],qf[s][3], bb.x, bb.y);
        MMAH(cg1, qf[s][0],qf[s][1],qf[s][2],qf[s][3], dd.x, dd.y);
    }
    float p00 = exp2f(cg0[0]), p01 = exp2f(cg0[1]);
    float p02 = exp2f(cg0[2]), p03 = exp2f(cg0[3]);
    float p10 = exp2f(cg1[0]), p11 = exp2f(cg1[1]);
    float p12 = exp2f(cg1[2]), p13 = exp2f(cg1[3]);
    sumlo += (p00 + p01) + (p10 + p11);
    sumhi += (p02 + p03) + (p12 + p13);
    u32 a0 = packh2(p00, p01);
    u32 a1 = packh2(p02, p03);
    u32 a2 = packh2(p10, p11);
    u32 a3 = packh2(p12, p13);
    const u32* vr = Vt + gid*KSTRW + 8*j + 2*tig;
    #pragma unroll
    for (int ge=0; ge<8; ge++){
        uint2 vv = *(const uint2*)(vr + ge*8*KSTRW);
        MMAH(o[ge], a0,a1,a2,a3, vv.x, vv.y);
    }
}

__device__ __forceinline__ void chunk_diag(
    const u32* Kt, const u32* Vt, const u32 qf[4][4], float o[8][4],
    float& sumlo, float& sumhi, int dj, int gid, int tig,
    int nb, int rlo, int rhi, int hist, float dloS, float dhiS)
{
    const u32* kb0 = Kt + (16*dj + gid)*KSTRW;
    const u32* kb1 = kb0 + 8*KSTRW;
    float cg0[4]={0.f,0.f,0.f,0.f}, cg1[4]={0.f,0.f,0.f,0.f};
    #pragma unroll
    for (int s=0;s<4;s++){
        uint2 bb = *(const uint2*)(kb0 + 8*s + 2*tig);
        uint2 dd = *(const uint2*)(kb1 + 8*s + 2*tig);
        MMAH(cg0, qf[s][0],qf[s][1],qf[s][2],qf[s][3], bb.x, bb.y);
        MMAH(cg1, qf[s][0],qf[s][1],qf[s][2],qf[s][3], dd.x, dd.y);
    }
    const int kb = nb + 16*dj;
    int c0 = kb + 2*tig, c1 = c0 + 1;
    int c2 = c0 + 8,     c3 = c1 + 8;
    float v00=cg0[0], v01=cg0[1], v02=cg0[2], v03=cg0[3];
    float v10=cg1[0], v11=cg1[1], v12=cg1[2], v13=cg1[3];
    if (rlo >= hist) {
        if (c0 == rlo) v00 = dloS;
        if (c1 == rlo) v01 = dloS;
        if (c2 == rlo) v10 = dloS;
        if (c3 == rlo) v11 = dloS;
        if (c0 == rhi) v02 = dhiS;
        if (c1 == rhi) v03 = dhiS;
        if (c2 == rhi) v12 = dhiS;
        if (c3 == rhi) v13 = dhiS;
    }
    float p00 = (c0 <= rlo) ? exp2f(v00) : 0.f;
    float p01 = (c1 <= rlo) ? exp2f(v01) : 0.f;
    float p02 = (c0 <= rhi) ? exp2f(v02) : 0.f;
    float p03 = (c1 <= rhi) ? exp2f(v03) : 0.f;
    float p10 = (c2 <= rlo) ? exp2f(v10) : 0.f;
    float p11 = (c3 <= rlo) ? exp2f(v11) : 0.f;
    float p12 = (c2 <= rhi) ? exp2f(v12) : 0.f;
    float p13 = (c3 <= rhi) ? exp2f(v13) : 0.f;
    sumlo += (p00 + p01) + (p10 + p11);
    sumhi += (p02 + p03) + (p12 + p13);
    u32 a0 = packh2(p00, p01);
    u32 a1 = packh2(p02, p03);
    u32 a2 = packh2(p10, p11);
    u32 a3 = packh2(p12, p13);
    const u32* vr = Vt + gid*KSTRW + 8*dj + 2*tig;
    #pragma unroll
    for (int ge=0; ge<8; ge++){
        uint2 vv = *(const uint2*)(vr + ge*8*KSTRW);
        MMAH(o[ge], a0,a1,a2,a3, vv.x, vv.y);
    }
}

// ------------------------------------------------------------------- main ----
__global__ void __launch_bounds__(NTH, 4)
ffcca_mma(const float* __restrict__ Q, const float* __restrict__ V,
          const float* __restrict__ Qd, const float* __restrict__ Kd,
          const float* __restrict__ Vd, const int* __restrict__ histp,
          float* __restrict__ Out)
{
    extern __shared__ char smem[];
    float* sdiag = (float*)(smem + SM_DIAG);
    u32 sb; asm("{ .reg .u64 x; cvta.to.shared.u64 x, %1; cvt.u32.u64 %0, x; }"
                : "=r"(sb) : "l"(smem));

    const int hist = *histp;                 // 512
    const int t = threadIdx.x;
    const int w = t >> 5, lane = t & 31;
    const int gid = lane >> 2, tig = lane & 3;
    const int bx = blockIdx.x, bh = blockIdx.y;
    const int b = bh >> 3, h = bh & 7;
    const size_t rs = (size_t)H_ * E_;
    const size_t base = (size_t)b * L_ * rs + (size_t)h * E_;

    const u32* KsrcB = g_Kh + (size_t)bh * L_ * 32;
    const u32* VsrcB = g_Vt + (size_t)bh * E_ * (L_/2);
    const int ldr = t >> 3, ldc = t & 7;

    #pragma unroll 1
    for (int ph = 0; ph < 2; ph++) {
        const int qt = ph ? bx : (2*GRIDX - 1 - bx);   // heavy tile first
        const int m0 = qt * BQ;
        const int wm0 = m0 + w*16;
        const int rlo = wm0 + gid;
        const int rhi = rlo + 8;

        // ---- exact fp32 diagonal scores for rows m0..m0+63 ----
        if (t < BQ) {
            int row = m0 + t;
            const float* qs = (row < hist) ? Q : Qd;
            const float4* qr = (const float4*)(qs + base + (size_t)row*rs);
            const float4* kr = (const float4*)(Kd + base + (size_t)row*rs);
            float a0=0,a1=0,a2=0,a3=0;
            #pragma unroll
            for (int c=0;c<16;c++){ float4 q4=qr[c], k4=kr[c];
                a0+=q4.x*k4.x; a1+=q4.y*k4.y; a2+=q4.z*k4.z; a3+=q4.w*k4.w; }
            sdiag[t] = (a0+a1)+(a2+a3);
        }

        // ---- Q fragments (fp16, pre-scaled by C2 -> log2-domain scores) ----
        u32 qf[4][4];
        {
            const float* qs = (rlo < hist) ? Q : Qd;
            const float* qlo = qs + base + (size_t)rlo*rs;
            const float* qhi = qs + base + (size_t)rhi*rs;
            #pragma unroll
            for (int s=0;s<4;s++){
                float2 x0 = *(const float2*)(qlo + 16*s + 2*tig);
                float2 x1 = *(const float2*)(qhi + 16*s + 2*tig);
                float2 x2 = *(const float2*)(qlo + 16*s + 8 + 2*tig);
                float2 x3 = *(const float2*)(qhi + 16*s + 8 + 2*tig);
                qf[s][0] = packh2(C2*x0.x, C2*x0.y);
                qf[s][1] = packh2(C2*x1.x, C2*x1.y);
                qf[s][2] = packh2(C2*x2.x, C2*x2.y);
                qf[s][3] = packh2(C2*x3.x, C2*x3.y);
            }
        }

        float o[8][4];
        #pragma unroll
        for (int j=0;j<8;j++){ o[j][0]=o[j][1]=o[j][2]=o[j][3]=0.f; }
        float sumlo=0.f, sumhi=0.f;

        const int ntiles = qt + 1;
        int cur = 0;

        // ---- prologue: issue tile 0 into buffer 0 ----
        {
            #pragma unroll
            for (int i=0;i<4;i++){
                int r = ldr + i*16;
                u32 doff = (r*KSTRW + ldc*4) * 4;
                CPA16(sb + SM_K + doff, KsrcB + (size_t)r*32 + ldc*4);
                CPA16(sb + SM_V + doff, VsrcB + (size_t)r*(L_/2) + ldc*4);
            }
            CPCOMMIT();
        }
        __syncthreads();                     // sdiag visible
        const float dloS = C2 * sdiag[rlo - m0];
        const float dhiS = C2 * sdiag[rhi - m0];

        #pragma unroll 1
        for (int nt = 0; nt < ntiles; nt++) {
            if (nt + 1 < ntiles) {
                const int nb2 = (nt+1) * BK;
                const u32* ks = KsrcB + (size_t)nb2*32;
                const u32* vs = VsrcB + (nb2 >> 1);
                const u32 bo = (cur^1) * (KBUFW*4);
                #pragma unroll
                for (int i=0;i<4;i++){
                    int r = ldr + i*16;
                    u32 doff = (r*KSTRW + ldc*4) * 4;
                    CPA16(sb + SM_K + bo + doff, ks + (size_t)r*32 + ldc*4);
                    CPA16(sb + SM_V + bo + doff, vs + (size_t)r*(L_/2) + ldc*4);
                }
                CPCOMMIT();
                CPWAIT(1);
            } else {
                CPWAIT(0);
            }
            __syncthreads();

            const u32* Kt = (const u32*)(smem + SM_K + cur*(KBUFW*4));
            const u32* Vt = (const u32*)(smem + SM_V + cur*(KBUFW*4));
            const int nb = nt * BK;
            const int dj = (wm0 - nb) >> 4;

            if (dj >= 4) {
                // fully-clean tile: branch-free straight-line, max ILP
                chunk_clean(Kt, Vt, qf, o, sumlo, sumhi, 0, gid, tig);
                chunk_clean(Kt, Vt, qf, o, sumlo, sumhi, 1, gid, tig);
                chunk_clean(Kt, Vt, qf, o, sumlo, sumhi, 2, gid, tig);
                chunk_clean(Kt, Vt, qf, o, sumlo, sumhi, 3, gid, tig);
            } else {
                #pragma unroll
                for (int j=0;j<3;j++) if (j < dj)
                    chunk_clean(Kt, Vt, qf, o, sumlo, sumhi, j, gid, tig);
                chunk_diag(Kt, Vt, qf, o, sumlo, sumhi, dj, gid, tig,
                           nb, rlo, rhi, hist, dloS, dhiS);
            }
            __syncthreads();
            cur ^= 1;
        }

        // ---- complete row sums across the 4-lane quad ----
        sumlo += __shfl_xor_sync(0xffffffffu, sumlo, 1);
        sumlo += __shfl_xor_sync(0xffffffffu, sumlo, 2);
        sumhi += __shfl_xor_sync(0xffffffffu, sumhi, 1);
        sumhi += __shfl_xor_sync(0xffffffffu, sumhi, 2);
        const float ilo = 1.f/sumlo, ihi = 1.f/sumhi;

        // ---- epilogue ----
        float* out_lo = Out + base + (size_t)rlo*rs;
        float* out_hi = Out + base + (size_t)rhi*rs;
        if (rlo >= hist) {
            const float pdlo = exp2f(dloS) * ilo;
            const float pdhi = exp2f(dhiS) * ihi;
            const float* vlo = V  + base + (size_t)rlo*rs;
            const float* vhi = V  + base + (size_t)rhi*rs;
            const float* dvlo = Vd + base + (size_t)rlo*rs;
            const float* dvhi = Vd + base + (size_t)rhi*rs;
            #pragma unroll
            for (int ge=0;ge<8;ge++){
                int col = 8*ge + 2*tig;
                float2 vl = *(const float2*)(vlo+col), dl = *(const float2*)(dvlo+col);
                float2 vh = *(const float2*)(vhi+col), dh = *(const float2*)(dvhi+col);
                float2 ol, oh;
                ol.x = o[ge][0]*ilo + pdlo*(dl.x - vl.x);
                ol.y = o[ge][1]*ilo + pdlo*(dl.y - vl.y);
                oh.x = o[ge][2]*ihi + pdhi*(dh.x - vh.x);
                oh.y = o[ge][3]*ihi + pdhi*(dh.y - vh.y);
                *(float2*)(out_lo+col) = ol;
                *(float2*)(out_hi+col) = oh;
            }
        } else {
            #pragma unroll
            for (int ge=0;ge<8;ge++){
                int col = 8*ge + 2*tig;
                *(float2*)(out_lo+col) = make_float2(o[ge][0]*ilo, o[ge][1]*ilo);
                *(float2*)(out_hi+col) = make_float2(o[ge][2]*ihi, o[ge][3]*ihi);
            }
        }
        __syncthreads();                     // phase boundary (sdiag reuse)
    }
}

extern "C" void kernel_launch(void* const* d_in, const int* in_sizes, int n_in,
                              void* d_out, int out_size) {
    const float* Q  = (const float*)d_in[0];
    const float* K  = (const float*)d_in[1];
    const float* V  = (const float*)d_in[2];
    const float* Qd = (const float*)d_in[3];
    const float* Kd = (const float*)d_in[4];
    const float* Vd = (const float*)d_in[5];
    const int* histp = (const int*)d_in[7];
    dim3 pg(L_/64, B_ * H_);
    prepack<<<pg, NTH>>>(K, V);
    cudaFuncSetAttribute(ffcca_mma, cudaFuncAttributeMaxDynamicSharedMemorySize, SMEM_TOTAL);
    dim3 grid(GRIDX, B_ * H_);
    ffcca_mma<<<grid, NTH, SMEM_TOTAL>>>(Q, V, Qd, Kd, Vd, histp, (float*)d_out);
}